// round 2
// baseline (speedup 1.0000x reference)
#include <cuda_runtime.h>
#include <math.h>

#define NMAX 50000
#define EMAX 800000
#define ALPHA 0.01f

// ---- static scratch (no allocations allowed) ----
__device__ float g_H1[(size_t)NMAX * 256];    // layer-1 features, head-major cols
__device__ float g_hcat[(size_t)NMAX * 256];  // elu(attention output), layer-2 input
__device__ float g_H2[(size_t)NMAX * 64];     // layer-2 features
__device__ float g_s1h[NMAX * 4];
__device__ float g_s2h[NMAX * 4];
__device__ float g_s1o[NMAX];
__device__ float g_s2o[NMAX];
__device__ int   g_count[NMAX];
__device__ int   g_rowptr[NMAX + 1];
__device__ int   g_cursor[NMAX];
__device__ int   g_col[EMAX];
__device__ int   g_idx64;                     // 1 if edge_index is int64, 0 if int32

// ---------------------------------------------------------------
// Probe edge_index dtype: int64 little-endian with values < 2^31
// has every odd 32-bit word == 0. Random int32 node ids don't.
// ---------------------------------------------------------------
__global__ void probe_dtype(const int* __restrict__ w, int E)
{
    int nCheck = 2 * E < 256 ? 2 * E : 256;   // words available >= 2E for either dtype
    int is64 = 1;
    for (int i = 1; i < nCheck; i += 2)
        if (w[i] != 0) { is64 = 0; break; }
    g_idx64 = is64;
}

// ---------------------------------------------------------------
// Tiled fp32 GEMM: C(M x 64*gridDim.y) = A(MxK) @ B-tiles(Kx64)
// outSel: 0 -> g_H1, 1 -> g_H2.  A==nullptr -> use g_hcat.
// ---------------------------------------------------------------
__global__ __launch_bounds__(256) void sgemm64(
    const float* __restrict__ A, int lda,
    const float* __restrict__ Ball, int bStride,
    int outSel, int ldc, int M, int K)
{
    __shared__ float As[16][68];
    __shared__ float Bs[16][68];

    const float* Ap = A ? A : g_hcat;
    float* C = (outSel == 0) ? g_H1 : g_H2;
    const float* B = Ball + (size_t)blockIdx.y * bStride;
    int row0 = blockIdx.x * 64;
    int colOff = blockIdx.y * 64;

    int tid = threadIdx.x;
    int tx = tid & 15, ty = tid >> 4;

    float acc[4][4];
#pragma unroll
    for (int i = 0; i < 4; i++)
#pragma unroll
        for (int j = 0; j < 4; j++) acc[i][j] = 0.f;

    int ar = tid >> 2;          // 0..63  (A tile row)
    int ak = (tid & 3) * 4;     // 0,4,8,12 (A tile k base)
    int br = tid >> 4;          // 0..15  (B tile row)
    int bc = (tid & 15) * 4;    // B tile col base

    for (int kb = 0; kb < K; kb += 16) {
        float4 av = make_float4(0.f, 0.f, 0.f, 0.f);
        if (row0 + ar < M)
            av = *(const float4*)(Ap + (size_t)(row0 + ar) * lda + kb + ak);
        As[ak + 0][ar] = av.x;
        As[ak + 1][ar] = av.y;
        As[ak + 2][ar] = av.z;
        As[ak + 3][ar] = av.w;

        float4 bv = *(const float4*)(B + (size_t)(kb + br) * 64 + bc);
        *(float4*)&Bs[br][bc] = bv;

        __syncthreads();
#pragma unroll
        for (int k = 0; k < 16; k++) {
            float a0 = As[k][ty * 4 + 0];
            float a1 = As[k][ty * 4 + 1];
            float a2 = As[k][ty * 4 + 2];
            float a3 = As[k][ty * 4 + 3];
            float4 b = *(const float4*)&Bs[k][tx * 4];
            acc[0][0] += a0 * b.x; acc[0][1] += a0 * b.y; acc[0][2] += a0 * b.z; acc[0][3] += a0 * b.w;
            acc[1][0] += a1 * b.x; acc[1][1] += a1 * b.y; acc[1][2] += a1 * b.z; acc[1][3] += a1 * b.w;
            acc[2][0] += a2 * b.x; acc[2][1] += a2 * b.y; acc[2][2] += a2 * b.z; acc[2][3] += a2 * b.w;
            acc[3][0] += a3 * b.x; acc[3][1] += a3 * b.y; acc[3][2] += a3 * b.z; acc[3][3] += a3 * b.w;
        }
        __syncthreads();
    }

#pragma unroll
    for (int i = 0; i < 4; i++) {
        int r = row0 + ty * 4 + i;
        if (r < M) {
            float4 v = make_float4(acc[i][0], acc[i][1], acc[i][2], acc[i][3]);
            *(float4*)(C + (size_t)r * ldc + colOff + tx * 4) = v;
        }
    }
}

// ---------------------------------------------------------------
// per-node attention score vectors, layer 1 (4 heads)
// ---------------------------------------------------------------
__global__ __launch_bounds__(256) void svec_heads(const float* __restrict__ attn, int N)
{
    int warp = (blockIdx.x * blockDim.x + threadIdx.x) >> 5;
    int lane = threadIdx.x & 31;
    if (warp >= N) return;
    const float* hrow = g_H1 + (size_t)warp * 256;
#pragma unroll
    for (int h = 0; h < 4; h++) {
        float ha = hrow[h * 64 + lane];
        float hb = hrow[h * 64 + 32 + lane];
        const float* a = attn + h * 128;
        float v1 = ha * a[lane] + hb * a[32 + lane];
        float v2 = ha * a[64 + lane] + hb * a[96 + lane];
#pragma unroll
        for (int off = 16; off; off >>= 1) {
            v1 += __shfl_xor_sync(0xffffffffu, v1, off);
            v2 += __shfl_xor_sync(0xffffffffu, v2, off);
        }
        if (lane == 0) {
            g_s1h[warp * 4 + h] = v1;
            g_s2h[warp * 4 + h] = v2;
        }
    }
}

// per-node score vectors, output layer
__global__ __launch_bounds__(256) void svec_out(const float* __restrict__ attn, int N)
{
    int warp = (blockIdx.x * blockDim.x + threadIdx.x) >> 5;
    int lane = threadIdx.x & 31;
    if (warp >= N) return;
    const float* hrow = g_H2 + (size_t)warp * 64;
    float ha = hrow[lane];
    float hb = hrow[32 + lane];
    float v1 = ha * attn[lane] + hb * attn[32 + lane];
    float v2 = ha * attn[64 + lane] + hb * attn[96 + lane];
#pragma unroll
    for (int off = 16; off; off >>= 1) {
        v1 += __shfl_xor_sync(0xffffffffu, v1, off);
        v2 += __shfl_xor_sync(0xffffffffu, v2, off);
    }
    if (lane == 0) {
        g_s1o[warp] = v1;
        g_s2o[warp] = v2;
    }
}

// ---------------------------------------------------------------
// CSR build (dtype-adaptive index decode)
// ---------------------------------------------------------------
__device__ __forceinline__ int load_idx(const int* __restrict__ w, int pos, int is64)
{
    return is64 ? w[2 * pos] : w[pos];
}

__global__ void zero_counts(int N)
{
    int i = blockIdx.x * blockDim.x + threadIdx.x;
    if (i < N) g_count[i] = 0;
}

__global__ void hist_kernel(const int* __restrict__ w, int E)
{
    int e = blockIdx.x * blockDim.x + threadIdx.x;
    if (e >= E) return;
    int src = load_idx(w, e, g_idx64);
    atomicAdd(&g_count[src], 1);
}

__global__ __launch_bounds__(1024) void scan_kernel(int n)
{
    __shared__ int sh[1024];
    __shared__ int carry_sh;
    if (threadIdx.x == 0) carry_sh = 0;
    __syncthreads();
    for (int base = 0; base < n; base += 1024) {
        int i = base + threadIdx.x;
        int v = (i < n) ? g_count[i] : 0;
        sh[threadIdx.x] = v;
        __syncthreads();
#pragma unroll
        for (int off = 1; off < 1024; off <<= 1) {
            int t = (threadIdx.x >= off) ? sh[threadIdx.x - off] : 0;
            __syncthreads();
            sh[threadIdx.x] += t;
            __syncthreads();
        }
        if (i < n) {
            int excl = carry_sh + sh[threadIdx.x] - v;
            g_rowptr[i] = excl;
            g_cursor[i] = excl;
        }
        __syncthreads();
        if (threadIdx.x == 1023) carry_sh += sh[1023];
        __syncthreads();
    }
    if (threadIdx.x == 0) g_rowptr[n] = carry_sh;
}

__global__ void scatter_kernel(const int* __restrict__ w, int E)
{
    int e = blockIdx.x * blockDim.x + threadIdx.x;
    if (e >= E) return;
    int is64 = g_idx64;
    int src = load_idx(w, e, is64);
    int dst = load_idx(w, E + e, is64);
    int pos = atomicAdd(&g_cursor[src], 1);
    g_col[pos] = dst;
}

// ---------------------------------------------------------------
// layer-1 attention + aggregation + ELU (warp per node, 4 heads)
// ---------------------------------------------------------------
__global__ __launch_bounds__(256) void agg_heads(int N)
{
    int warp = (blockIdx.x * blockDim.x + threadIdx.x) >> 5;
    int lane = threadIdx.x & 31;
    if (warp >= N) return;

    int e0 = g_rowptr[warp];
    int e1 = g_rowptr[warp + 1];
    float4 s1v = *(const float4*)&g_s1h[warp * 4];
    float s1a[4] = {s1v.x, s1v.y, s1v.z, s1v.w};

    float m[4], l[4], acc[8];
#pragma unroll
    for (int h = 0; h < 4; h++) { m[h] = -1e30f; l[h] = 0.f; }
#pragma unroll
    for (int i = 0; i < 8; i++) acc[i] = 0.f;

    for (int e = e0; e < e1; e++) {
        int dst = g_col[e];
        float4 s2v = *(const float4*)&g_s2h[dst * 4];
        float s2a[4] = {s2v.x, s2v.y, s2v.z, s2v.w};
        const float* hr = g_H1 + (size_t)dst * 256;
#pragma unroll
        for (int h = 0; h < 4; h++) {
            float sv = s1a[h] + s2a[h];
            float sc = -(sv > 0.f ? sv : ALPHA * sv);
            float ha = hr[h * 64 + lane];
            float hb = hr[h * 64 + 32 + lane];
            if (sc <= m[h]) {                 // warp-uniform branch
                float p = __expf(sc - m[h]);
                l[h] += p;
                acc[2 * h]     += p * ha;
                acc[2 * h + 1] += p * hb;
            } else {
                float s = __expf(m[h] - sc);
                l[h] = l[h] * s + 1.f;
                acc[2 * h]     = acc[2 * h] * s + ha;
                acc[2 * h + 1] = acc[2 * h + 1] * s + hb;
                m[h] = sc;
            }
        }
    }

    float* orow = g_hcat + (size_t)warp * 256;
    bool has = (e1 > e0);
#pragma unroll
    for (int h = 0; h < 4; h++) {
        float va = 0.f, vb = 0.f;
        if (has) {
            float inv = 1.f / l[h];
            va = acc[2 * h] * inv;
            vb = acc[2 * h + 1] * inv;
        }
        va = (va > 0.f) ? va : (__expf(va) - 1.f);   // ELU
        vb = (vb > 0.f) ? vb : (__expf(vb) - 1.f);
        orow[h * 64 + lane] = va;
        orow[h * 64 + 32 + lane] = vb;
    }
}

// ---------------------------------------------------------------
// output-layer attention + aggregation (warp per node, dim 64)
// ---------------------------------------------------------------
__global__ __launch_bounds__(256) void agg_out(float* __restrict__ out, int N)
{
    int warp = (blockIdx.x * blockDim.x + threadIdx.x) >> 5;
    int lane = threadIdx.x & 31;
    if (warp >= N) return;

    int e0 = g_rowptr[warp];
    int e1 = g_rowptr[warp + 1];
    float s1 = g_s1o[warp];

    float m = -1e30f, l = 0.f, a0 = 0.f, a1 = 0.f;
    for (int e = e0; e < e1; e++) {
        int dst = g_col[e];
        float sv = s1 + g_s2o[dst];
        float sc = -(sv > 0.f ? sv : ALPHA * sv);
        const float* hr = g_H2 + (size_t)dst * 64;
        float ha = hr[lane];
        float hb = hr[32 + lane];
        if (sc <= m) {
            float p = __expf(sc - m);
            l += p;
            a0 += p * ha;
            a1 += p * hb;
        } else {
            float s = __expf(m - sc);
            l = l * s + 1.f;
            a0 = a0 * s + ha;
            a1 = a1 * s + hb;
            m = sc;
        }
    }
    float va = 0.f, vb = 0.f;
    if (e1 > e0) {
        float inv = 1.f / l;
        va = a0 * inv;
        vb = a1 * inv;
    }
    out[(size_t)warp * 64 + lane] = va;
    out[(size_t)warp * 64 + 32 + lane] = vb;
}

// ---------------------------------------------------------------
extern "C" void kernel_launch(void* const* d_in, const int* in_sizes, int n_in,
                              void* d_out, int out_size)
{
    const float* x          = (const float*)d_in[0];
    const int*   ei_w       = (const int*)d_in[1];   // 32-bit word view of edge_index
    const float* W_heads    = (const float*)d_in[2];
    const float* attn_heads = (const float*)d_in[3];
    const float* W_out      = (const float*)d_in[4];
    const float* attn_out   = (const float*)d_in[5];
    float* out = (float*)d_out;

    int N = in_sizes[0] / 128;
    int E = in_sizes[1] / 2;

    int nodeWarpBlocks = (N + 7) / 8;         // 8 warps per 256-thread block
    int edgeBlocks = (E + 255) / 256;
    int nBlocks = (N + 255) / 256;

    // dtype probe (int32 vs int64 edge_index)
    probe_dtype<<<1, 1>>>(ei_w, E);

    // GEMM1: H1 = x @ Wcat   (4 head tiles of 128x64)
    dim3 g1((N + 63) / 64, 4);
    sgemm64<<<g1, 256>>>(x, 128, W_heads, 128 * 64, /*outSel=*/0, 256, N, 128);

    // score vectors, layer 1
    svec_heads<<<nodeWarpBlocks, 256>>>(attn_heads, N);

    // CSR build (by src)
    zero_counts<<<nBlocks, 256>>>(N);
    hist_kernel<<<edgeBlocks, 256>>>(ei_w, E);
    scan_kernel<<<1, 1024>>>(N);
    scatter_kernel<<<edgeBlocks, 256>>>(ei_w, E);

    // layer-1 softmax+aggregate+ELU -> g_hcat
    agg_heads<<<nodeWarpBlocks, 256>>>(N);

    // GEMM2: H2 = hcat @ W_out
    dim3 g2((N + 63) / 64, 1);
    sgemm64<<<g2, 256>>>(nullptr, 256, W_out, 0, /*outSel=*/1, 64, N, 256);

    // score vectors + final aggregation
    svec_out<<<nodeWarpBlocks, 256>>>(attn_out, N);
    agg_out<<<nodeWarpBlocks, 256>>>(out, N);
}

// round 3
// speedup vs baseline: 1.4030x; 1.4030x over previous
#include <cuda_runtime.h>
#include <math.h>

#define NMAX 50000
#define EMAX 800000
#define ALPHA 0.01f

// ---- static scratch (no allocations allowed) ----
__device__ float g_H1[(size_t)NMAX * 256];    // layer-1 features, head-major cols
__device__ float g_hcat[(size_t)NMAX * 256];  // elu(attention output), layer-2 input
__device__ float g_H2[(size_t)NMAX * 64];     // layer-2 features
__device__ float g_s1h[NMAX * 4];
__device__ float g_s2h[NMAX * 4];
__device__ float g_s1o[NMAX];
__device__ float g_s2o[NMAX];
__device__ int   g_count[NMAX];
__device__ int   g_rowptr[NMAX + 1];
__device__ int   g_cursor[NMAX];
__device__ int   g_col[EMAX];
__device__ int   g_idx64;                     // 1 if edge_index is int64, 0 if int32
__device__ int   g_bsum[64];
__device__ int   g_boff[64];

// ---------------------------------------------------------------
// Probe edge_index dtype: int64 little-endian with values < 2^31
// has every odd 32-bit word == 0. Random int32 node ids don't.
// ---------------------------------------------------------------
__global__ void probe_dtype(const int* __restrict__ w, int E)
{
    int nCheck = 2 * E < 256 ? 2 * E : 256;
    int is64 = 1;
    for (int i = 1; i < nCheck; i += 2)
        if (w[i] != 0) { is64 = 0; break; }
    g_idx64 = is64;
}

// ---------------------------------------------------------------
// tf32 tensor-core GEMM: C(M x 64*gridDim.y) = A(MxK) @ B-tiles(Kx64)
// Block = 128 rows x 64 cols, 8 warps (16 rows each).
// outSel: 0 -> g_H1, 1 -> g_H2.  A==nullptr -> use g_hcat.
// Requires K % 128 == 0 (true: 128 / 256).
// ---------------------------------------------------------------
__device__ __forceinline__ unsigned f2tf32(float f)
{
    unsigned u;
    asm("cvt.rna.tf32.f32 %0, %1;" : "=r"(u) : "f"(f));
    return u;
}

__device__ __forceinline__ void mma_tf32(
    float& d0, float& d1, float& d2, float& d3,
    unsigned a0, unsigned a1, unsigned a2, unsigned a3,
    unsigned b0, unsigned b1)
{
    asm volatile(
        "mma.sync.aligned.m16n8k8.row.col.f32.tf32.tf32.f32 "
        "{%0,%1,%2,%3}, {%4,%5,%6,%7}, {%8,%9}, {%0,%1,%2,%3};\n"
        : "+f"(d0), "+f"(d1), "+f"(d2), "+f"(d3)
        : "r"(a0), "r"(a1), "r"(a2), "r"(a3), "r"(b0), "r"(b1));
}

__global__ __launch_bounds__(256) void tf32_gemm(
    const float* __restrict__ A, int lda,
    const float* __restrict__ Ball, int bStride,
    int outSel, int ldc, int M, int K)
{
    __shared__ unsigned As[128][20];   // 16-k chunk of A, padded (banks = (20r+k)%32, conflict-free)
    __shared__ unsigned Bs[128][72];   // 128-k chunk of B, padded (banks = (8q+n)%32, conflict-free)

    const float* Ap = A ? A : g_hcat;
    float* C = (outSel == 0) ? g_H1 : g_H2;
    const float* B = Ball + (size_t)blockIdx.y * bStride;
    int row0 = blockIdx.x * 128;
    int colOff = blockIdx.y * 64;

    int tid = threadIdx.x;
    int lane = tid & 31, w = tid >> 5;
    int gid = lane >> 2, qid = lane & 3;

    float acc[8][4];
#pragma unroll
    for (int i = 0; i < 8; i++)
#pragma unroll
        for (int j = 0; j < 4; j++) acc[i][j] = 0.f;

    for (int kc = 0; kc < K; kc += 128) {
        if (kc) __syncthreads();               // done computing with old Bs
        // stage B chunk (128 x 64), cvt to tf32
        for (int i = tid; i < 128 * 16; i += 256) {
            int br = i >> 4, bc4 = (i & 15) * 4;
            float4 bv = *(const float4*)(B + (size_t)(kc + br) * 64 + bc4);
            Bs[br][bc4 + 0] = f2tf32(bv.x);
            Bs[br][bc4 + 1] = f2tf32(bv.y);
            Bs[br][bc4 + 2] = f2tf32(bv.z);
            Bs[br][bc4 + 3] = f2tf32(bv.w);
        }

        for (int ks = 0; ks < 128; ks += 16) {
            if (ks) __syncthreads();           // done computing with old As
            // stage A chunk (128 rows x 16 k), cvt to tf32
#pragma unroll
            for (int i = 0; i < 2; i++) {
                int u = tid + i * 256;
                int ar = u >> 2, c4 = (u & 3) * 4;
                float4 av = make_float4(0.f, 0.f, 0.f, 0.f);
                if (row0 + ar < M)
                    av = *(const float4*)(Ap + (size_t)(row0 + ar) * lda + kc + ks + c4);
                As[ar][c4 + 0] = f2tf32(av.x);
                As[ar][c4 + 1] = f2tf32(av.y);
                As[ar][c4 + 2] = f2tf32(av.z);
                As[ar][c4 + 3] = f2tf32(av.w);
            }
            __syncthreads();                   // As (and Bs on first ks) visible

#pragma unroll
            for (int k8 = 0; k8 < 16; k8 += 8) {
                unsigned a0 = As[w * 16 + gid][k8 + qid];
                unsigned a1 = As[w * 16 + gid + 8][k8 + qid];
                unsigned a2 = As[w * 16 + gid][k8 + qid + 4];
                unsigned a3 = As[w * 16 + gid + 8][k8 + qid + 4];
                int krow = ks + k8 + qid;
#pragma unroll
                for (int n0 = 0; n0 < 8; n0++) {
                    unsigned b0 = Bs[krow][n0 * 8 + gid];
                    unsigned b1 = Bs[krow + 4][n0 * 8 + gid];
                    mma_tf32(acc[n0][0], acc[n0][1], acc[n0][2], acc[n0][3],
                             a0, a1, a2, a3, b0, b1);
                }
            }
        }
    }

    // epilogue
    int r1 = row0 + w * 16 + gid;
    int r2 = r1 + 8;
#pragma unroll
    for (int n0 = 0; n0 < 8; n0++) {
        int c = colOff + n0 * 8 + 2 * qid;
        if (r1 < M) {
            float2 v = make_float2(acc[n0][0], acc[n0][1]);
            *(float2*)(C + (size_t)r1 * ldc + c) = v;
        }
        if (r2 < M) {
            float2 v = make_float2(acc[n0][2], acc[n0][3]);
            *(float2*)(C + (size_t)r2 * ldc + c) = v;
        }
    }
}

// ---------------------------------------------------------------
// per-node attention score vectors, layer 1 (4 heads)
// ---------------------------------------------------------------
__global__ __launch_bounds__(256) void svec_heads(const float* __restrict__ attn, int N)
{
    int warp = (blockIdx.x * blockDim.x + threadIdx.x) >> 5;
    int lane = threadIdx.x & 31;
    if (warp >= N) return;
    const float* hrow = g_H1 + (size_t)warp * 256;
#pragma unroll
    for (int h = 0; h < 4; h++) {
        float ha = hrow[h * 64 + lane];
        float hb = hrow[h * 64 + 32 + lane];
        const float* a = attn + h * 128;
        float v1 = ha * a[lane] + hb * a[32 + lane];
        float v2 = ha * a[64 + lane] + hb * a[96 + lane];
#pragma unroll
        for (int off = 16; off; off >>= 1) {
            v1 += __shfl_xor_sync(0xffffffffu, v1, off);
            v2 += __shfl_xor_sync(0xffffffffu, v2, off);
        }
        if (lane == 0) {
            g_s1h[warp * 4 + h] = v1;
            g_s2h[warp * 4 + h] = v2;
        }
    }
}

// per-node score vectors, output layer
__global__ __launch_bounds__(256) void svec_out(const float* __restrict__ attn, int N)
{
    int warp = (blockIdx.x * blockDim.x + threadIdx.x) >> 5;
    int lane = threadIdx.x & 31;
    if (warp >= N) return;
    const float* hrow = g_H2 + (size_t)warp * 64;
    float ha = hrow[lane];
    float hb = hrow[32 + lane];
    float v1 = ha * attn[lane] + hb * attn[32 + lane];
    float v2 = ha * attn[64 + lane] + hb * attn[96 + lane];
#pragma unroll
    for (int off = 16; off; off >>= 1) {
        v1 += __shfl_xor_sync(0xffffffffu, v1, off);
        v2 += __shfl_xor_sync(0xffffffffu, v2, off);
    }
    if (lane == 0) {
        g_s1o[warp] = v1;
        g_s2o[warp] = v2;
    }
}

// ---------------------------------------------------------------
// CSR build (dtype-adaptive index decode)
// ---------------------------------------------------------------
__device__ __forceinline__ int load_idx(const int* __restrict__ w, int pos, int is64)
{
    return is64 ? w[2 * pos] : w[pos];
}

__global__ void zero_counts(int N)
{
    int i = blockIdx.x * blockDim.x + threadIdx.x;
    if (i < N) g_count[i] = 0;
}

__global__ void hist_kernel(const int* __restrict__ w, int E)
{
    int e = blockIdx.x * blockDim.x + threadIdx.x;
    if (e >= E) return;
    int src = load_idx(w, e, g_idx64);
    atomicAdd(&g_count[src], 1);
}

// ---- 3-phase parallel exclusive scan over g_count -> g_rowptr/g_cursor ----
__global__ __launch_bounds__(1024) void scan_p1(int n)
{
    __shared__ int wsum[32];
    int t = threadIdx.x;
    int i = blockIdx.x * 1024 + t;
    int v = (i < n) ? g_count[i] : 0;
    int lane = t & 31, w = t >> 5;

    int x = v;
#pragma unroll
    for (int off = 1; off < 32; off <<= 1) {
        int y = __shfl_up_sync(0xffffffffu, x, off);
        if (lane >= off) x += y;
    }
    if (lane == 31) wsum[w] = x;
    __syncthreads();
    if (w == 0) {
        int z = wsum[lane];
#pragma unroll
        for (int off = 1; off < 32; off <<= 1) {
            int y = __shfl_up_sync(0xffffffffu, z, off);
            if (lane >= off) z += y;
        }
        wsum[lane] = z;
    }
    __syncthreads();
    int excl = x - v + (w > 0 ? wsum[w - 1] : 0);
    if (i < n) g_rowptr[i] = excl;
    if (t == 1023) g_bsum[blockIdx.x] = excl + v;   // block total
}

__global__ void scan_p2(int nb, int n)
{
    __shared__ int w0tot;
    int t = threadIdx.x;                             // 64 threads
    int v = (t < nb) ? g_bsum[t] : 0;
    int lane = t & 31, w = t >> 5;
    int x = v;
#pragma unroll
    for (int off = 1; off < 32; off <<= 1) {
        int y = __shfl_up_sync(0xffffffffu, x, off);
        if (lane >= off) x += y;
    }
    if (t == 31) w0tot = x;
    __syncthreads();
    int incl = x + (w ? w0tot : 0);
    if (t < nb) g_boff[t] = incl - v;
    if (t == nb - 1) g_rowptr[n] = incl;
}

__global__ __launch_bounds__(1024) void scan_p3(int n)
{
    int i = blockIdx.x * 1024 + threadIdx.x;
    if (i >= n) return;
    int val = g_rowptr[i] + g_boff[blockIdx.x];
    g_rowptr[i] = val;
    g_cursor[i] = val;
}

__global__ void scatter_kernel(const int* __restrict__ w, int E)
{
    int e = blockIdx.x * blockDim.x + threadIdx.x;
    if (e >= E) return;
    int is64 = g_idx64;
    int src = load_idx(w, e, is64);
    int dst = load_idx(w, E + e, is64);
    int pos = atomicAdd(&g_cursor[src], 1);
    g_col[pos] = dst;
}

// ---------------------------------------------------------------
// layer-1 attention + aggregation + ELU (warp per node, 4 heads)
// ---------------------------------------------------------------
__global__ __launch_bounds__(256) void agg_heads(int N)
{
    int warp = (blockIdx.x * blockDim.x + threadIdx.x) >> 5;
    int lane = threadIdx.x & 31;
    if (warp >= N) return;

    int e0 = g_rowptr[warp];
    int e1 = g_rowptr[warp + 1];
    float4 s1v = *(const float4*)&g_s1h[warp * 4];
    float s1a[4] = {s1v.x, s1v.y, s1v.z, s1v.w};

    float m[4], l[4], acc[8];
#pragma unroll
    for (int h = 0; h < 4; h++) { m[h] = -1e30f; l[h] = 0.f; }
#pragma unroll
    for (int i = 0; i < 8; i++) acc[i] = 0.f;

    for (int e = e0; e < e1; e++) {
        int dst = g_col[e];
        float4 s2v = *(const float4*)&g_s2h[dst * 4];
        float s2a[4] = {s2v.x, s2v.y, s2v.z, s2v.w};
        const float* hr = g_H1 + (size_t)dst * 256;
#pragma unroll
        for (int h = 0; h < 4; h++) {
            float sv = s1a[h] + s2a[h];
            float sc = -(sv > 0.f ? sv : ALPHA * sv);
            float ha = hr[h * 64 + lane];
            float hb = hr[h * 64 + 32 + lane];
            if (sc <= m[h]) {                 // warp-uniform branch
                float p = __expf(sc - m[h]);
                l[h] += p;
                acc[2 * h]     += p * ha;
                acc[2 * h + 1] += p * hb;
            } else {
                float s = __expf(m[h] - sc);
                l[h] = l[h] * s + 1.f;
                acc[2 * h]     = acc[2 * h] * s + ha;
                acc[2 * h + 1] = acc[2 * h + 1] * s + hb;
                m[h] = sc;
            }
        }
    }

    float* orow = g_hcat + (size_t)warp * 256;
    bool has = (e1 > e0);
#pragma unroll
    for (int h = 0; h < 4; h++) {
        float va = 0.f, vb = 0.f;
        if (has) {
            float inv = 1.f / l[h];
            va = acc[2 * h] * inv;
            vb = acc[2 * h + 1] * inv;
        }
        va = (va > 0.f) ? va : (__expf(va) - 1.f);   // ELU
        vb = (vb > 0.f) ? vb : (__expf(vb) - 1.f);
        orow[h * 64 + lane] = va;
        orow[h * 64 + 32 + lane] = vb;
    }
}

// ---------------------------------------------------------------
// output-layer attention + aggregation (warp per node, dim 64)
// ---------------------------------------------------------------
__global__ __launch_bounds__(256) void agg_out(float* __restrict__ out, int N)
{
    int warp = (blockIdx.x * blockDim.x + threadIdx.x) >> 5;
    int lane = threadIdx.x & 31;
    if (warp >= N) return;

    int e0 = g_rowptr[warp];
    int e1 = g_rowptr[warp + 1];
    float s1 = g_s1o[warp];

    float m = -1e30f, l = 0.f, a0 = 0.f, a1 = 0.f;
    for (int e = e0; e < e1; e++) {
        int dst = g_col[e];
        float sv = s1 + g_s2o[dst];
        float sc = -(sv > 0.f ? sv : ALPHA * sv);
        const float* hr = g_H2 + (size_t)dst * 64;
        float ha = hr[lane];
        float hb = hr[32 + lane];
        if (sc <= m) {
            float p = __expf(sc - m);
            l += p;
            a0 += p * ha;
            a1 += p * hb;
        } else {
            float s = __expf(m - sc);
            l = l * s + 1.f;
            a0 = a0 * s + ha;
            a1 = a1 * s + hb;
            m = sc;
        }
    }
    float va = 0.f, vb = 0.f;
    if (e1 > e0) {
        float inv = 1.f / l;
        va = a0 * inv;
        vb = a1 * inv;
    }
    out[(size_t)warp * 64 + lane] = va;
    out[(size_t)warp * 64 + 32 + lane] = vb;
}

// ---------------------------------------------------------------
extern "C" void kernel_launch(void* const* d_in, const int* in_sizes, int n_in,
                              void* d_out, int out_size)
{
    const float* x          = (const float*)d_in[0];
    const int*   ei_w       = (const int*)d_in[1];   // 32-bit word view of edge_index
    const float* W_heads    = (const float*)d_in[2];
    const float* attn_heads = (const float*)d_in[3];
    const float* W_out      = (const float*)d_in[4];
    const float* attn_out   = (const float*)d_in[5];
    float* out = (float*)d_out;

    int N = in_sizes[0] / 128;
    int E = in_sizes[1] / 2;

    int nodeWarpBlocks = (N + 7) / 8;         // 8 warps per 256-thread block
    int edgeBlocks = (E + 255) / 256;
    int nBlocks = (N + 255) / 256;
    int scanBlocks = (N + 1023) / 1024;

    // dtype probe (int32 vs int64 edge_index)
    probe_dtype<<<1, 1>>>(ei_w, E);

    // GEMM1: H1 = x @ Wcat   (4 head tiles of 128x64)
    dim3 g1((N + 127) / 128, 4);
    tf32_gemm<<<g1, 256>>>(x, 128, W_heads, 128 * 64, /*outSel=*/0, 256, N, 128);

    // score vectors, layer 1
    svec_heads<<<nodeWarpBlocks, 256>>>(attn_heads, N);

    // CSR build (by src)
    zero_counts<<<nBlocks, 256>>>(N);
    hist_kernel<<<edgeBlocks, 256>>>(ei_w, E);
    scan_p1<<<scanBlocks, 1024>>>(N);
    scan_p2<<<1, 64>>>(scanBlocks, N);
    scan_p3<<<scanBlocks, 1024>>>(N);
    scatter_kernel<<<edgeBlocks, 256>>>(ei_w, E);

    // layer-1 softmax+aggregate+ELU -> g_hcat
    agg_heads<<<nodeWarpBlocks, 256>>>(N);

    // GEMM2: H2 = hcat @ W_out
    dim3 g2((N + 127) / 128, 1);
    tf32_gemm<<<g2, 256>>>(nullptr, 256, W_out, 0, /*outSel=*/1, 64, N, 256);

    // score vectors + final aggregation
    svec_out<<<nodeWarpBlocks, 256>>>(attn_out, N);
    agg_out<<<nodeWarpBlocks, 256>>>(out, N);
}

// round 4
// speedup vs baseline: 1.5674x; 1.1171x over previous
#include <cuda_runtime.h>
#include <cuda_fp16.h>
#include <math.h>

#define NMAX 50000
#define EMAX 800000
#define ALPHA 0.01f

// ---- static scratch (no allocations allowed) ----
__device__ __half2 g_H1h[(size_t)NMAX * 128]; // layer-1 features fp16, head-major (256 halves/row)
__device__ __half2 g_H2h[(size_t)NMAX * 32];  // layer-2 features fp16 (64 halves/row)
__device__ float g_hcat[(size_t)NMAX * 256];  // elu(attention output), layer-2 input (fp32)
__device__ float g_s1h[NMAX * 4];
__device__ float g_s2h[NMAX * 4];
__device__ float g_s1o[NMAX];
__device__ float g_s2o[NMAX];
__device__ int   g_count[NMAX];               // .bss zero-init; scan_p1 re-zeroes each call
__device__ int   g_rowptr[NMAX + 1];
__device__ int   g_cursor[NMAX];
__device__ int   g_col[EMAX];
__device__ int   g_idx64;
__device__ int   g_bsum[64];

// ---------------------------------------------------------------
__global__ void probe_dtype(const int* __restrict__ w, int E)
{
    int nCheck = 2 * E < 256 ? 2 * E : 256;
    int is64 = 1;
    for (int i = 1; i < nCheck; i += 2)
        if (w[i] != 0) { is64 = 0; break; }
    g_idx64 = is64;
}

// ---------------------------------------------------------------
// tf32 tensor-core GEMM with fused epilogue:
//   - writes fp16 feature mirror (g_H1h / g_H2h)
//   - computes per-row attention score dots s1/s2 (quad shuffle reduce)
// layer 0: A(Mx128)=x, B=W_heads tile per blockIdx.y (4 heads)
// layer 1: A(Mx256)=g_hcat, B=W_out
// ---------------------------------------------------------------
__device__ __forceinline__ unsigned f2tf32(float f)
{
    unsigned u;
    asm("cvt.rna.tf32.f32 %0, %1;" : "=r"(u) : "f"(f));
    return u;
}

__device__ __forceinline__ void mma_tf32(
    float& d0, float& d1, float& d2, float& d3,
    unsigned a0, unsigned a1, unsigned a2, unsigned a3,
    unsigned b0, unsigned b1)
{
    asm volatile(
        "mma.sync.aligned.m16n8k8.row.col.f32.tf32.tf32.f32 "
        "{%0,%1,%2,%3}, {%4,%5,%6,%7}, {%8,%9}, {%0,%1,%2,%3};\n"
        : "+f"(d0), "+f"(d1), "+f"(d2), "+f"(d3)
        : "r"(a0), "r"(a1), "r"(a2), "r"(a3), "r"(b0), "r"(b1));
}

__global__ __launch_bounds__(256) void tf32_gemm(
    const float* __restrict__ A, int lda,
    const float* __restrict__ B0, int bStride,
    const float* __restrict__ attn, int layer, int M, int K)
{
    __shared__ unsigned As[128][20];
    __shared__ unsigned Bs[128][72];

    const float* Ap = A ? A : g_hcat;
    int head = blockIdx.y;
    const float* B = B0 + (size_t)head * bStride;
    int row0 = blockIdx.x * 128;

    int tid = threadIdx.x;
    int lane = tid & 31, w = tid >> 5;
    int gid = lane >> 2, qid = lane & 3;

    float acc[8][4];
#pragma unroll
    for (int i = 0; i < 8; i++)
#pragma unroll
        for (int j = 0; j < 4; j++) acc[i][j] = 0.f;

    for (int kc = 0; kc < K; kc += 128) {
        if (kc) __syncthreads();
        for (int i = tid; i < 128 * 16; i += 256) {
            int br = i >> 4, bc4 = (i & 15) * 4;
            float4 bv = *(const float4*)(B + (size_t)(kc + br) * 64 + bc4);
            Bs[br][bc4 + 0] = f2tf32(bv.x);
            Bs[br][bc4 + 1] = f2tf32(bv.y);
            Bs[br][bc4 + 2] = f2tf32(bv.z);
            Bs[br][bc4 + 3] = f2tf32(bv.w);
        }

        for (int ks = 0; ks < 128; ks += 16) {
            if (ks) __syncthreads();
#pragma unroll
            for (int i = 0; i < 2; i++) {
                int u = tid + i * 256;
                int ar = u >> 2, c4 = (u & 3) * 4;
                float4 av = make_float4(0.f, 0.f, 0.f, 0.f);
                if (row0 + ar < M)
                    av = *(const float4*)(Ap + (size_t)(row0 + ar) * lda + kc + ks + c4);
                As[ar][c4 + 0] = f2tf32(av.x);
                As[ar][c4 + 1] = f2tf32(av.y);
                As[ar][c4 + 2] = f2tf32(av.z);
                As[ar][c4 + 3] = f2tf32(av.w);
            }
            __syncthreads();

#pragma unroll
            for (int k8 = 0; k8 < 16; k8 += 8) {
                unsigned a0 = As[w * 16 + gid][k8 + qid];
                unsigned a1 = As[w * 16 + gid + 8][k8 + qid];
                unsigned a2 = As[w * 16 + gid][k8 + qid + 4];
                unsigned a3 = As[w * 16 + gid + 8][k8 + qid + 4];
                int krow = ks + k8 + qid;
#pragma unroll
                for (int n0 = 0; n0 < 8; n0++) {
                    unsigned b0 = Bs[krow][n0 * 8 + gid];
                    unsigned b1 = Bs[krow + 4][n0 * 8 + gid];
                    mma_tf32(acc[n0][0], acc[n0][1], acc[n0][2], acc[n0][3],
                             a0, a1, a2, a3, b0, b1);
                }
            }
        }
    }

    // ---- fused epilogue ----
    __half2* Hh2;
    int ldH2, colBase2, sStride, sOff;
    float *s1g, *s2g;
    const float* a1;
    if (layer == 0) {
        Hh2 = g_H1h; ldH2 = 128; colBase2 = head * 32;
        sStride = 4; sOff = head; s1g = g_s1h; s2g = g_s2h;
        a1 = attn + head * 128;
    } else {
        Hh2 = g_H2h; ldH2 = 32; colBase2 = 0;
        sStride = 1; sOff = 0; s1g = g_s1o; s2g = g_s2o;
        a1 = attn;
    }
    const float* a2v = a1 + 64;

    int r1 = row0 + w * 16 + gid;
    int r2 = r1 + 8;

    float p1a = 0.f, p2a = 0.f, p1b = 0.f, p2b = 0.f;
#pragma unroll
    for (int n0 = 0; n0 < 8; n0++) {
        int c0 = n0 * 8 + 2 * qid;
        float w10 = __ldg(a1 + c0), w11 = __ldg(a1 + c0 + 1);
        float w20 = __ldg(a2v + c0), w21 = __ldg(a2v + c0 + 1);
        p1a += acc[n0][0] * w10 + acc[n0][1] * w11;
        p2a += acc[n0][0] * w20 + acc[n0][1] * w21;
        p1b += acc[n0][2] * w10 + acc[n0][3] * w11;
        p2b += acc[n0][2] * w20 + acc[n0][3] * w21;
    }
#pragma unroll
    for (int off = 1; off < 4; off <<= 1) {
        p1a += __shfl_xor_sync(0xffffffffu, p1a, off);
        p2a += __shfl_xor_sync(0xffffffffu, p2a, off);
        p1b += __shfl_xor_sync(0xffffffffu, p1b, off);
        p2b += __shfl_xor_sync(0xffffffffu, p2b, off);
    }
    if (qid == 0) {
        if (r1 < M) { s1g[r1 * sStride + sOff] = p1a; s2g[r1 * sStride + sOff] = p2a; }
        if (r2 < M) { s1g[r2 * sStride + sOff] = p1b; s2g[r2 * sStride + sOff] = p2b; }
    }

#pragma unroll
    for (int n0 = 0; n0 < 8; n0++) {
        int cc = colBase2 + n0 * 4 + qid;
        if (r1 < M)
            Hh2[(size_t)r1 * ldH2 + cc] = __floats2half2_rn(acc[n0][0], acc[n0][1]);
        if (r2 < M)
            Hh2[(size_t)r2 * ldH2 + cc] = __floats2half2_rn(acc[n0][2], acc[n0][3]);
    }
}

// ---------------------------------------------------------------
// CSR build
// ---------------------------------------------------------------
__device__ __forceinline__ int load_idx(const int* __restrict__ w, int pos, int is64)
{
    return is64 ? w[2 * pos] : w[pos];
}

__global__ void hist_kernel(const int* __restrict__ w, int E)
{
    int e = blockIdx.x * blockDim.x + threadIdx.x;
    if (e >= E) return;
    int src = load_idx(w, e, g_idx64);
    atomicAdd(&g_count[src], 1);
}

__global__ __launch_bounds__(1024) void scan_p1(int n)
{
    __shared__ int wsum[32];
    int t = threadIdx.x;
    int i = blockIdx.x * 1024 + t;
    int v = (i < n) ? g_count[i] : 0;
    if (i < n) g_count[i] = 0;            // self-clear for next call
    int lane = t & 31, w = t >> 5;

    int x = v;
#pragma unroll
    for (int off = 1; off < 32; off <<= 1) {
        int y = __shfl_up_sync(0xffffffffu, x, off);
        if (lane >= off) x += y;
    }
    if (lane == 31) wsum[w] = x;
    __syncthreads();
    if (w == 0) {
        int z = wsum[lane];
#pragma unroll
        for (int off = 1; off < 32; off <<= 1) {
            int y = __shfl_up_sync(0xffffffffu, z, off);
            if (lane >= off) z += y;
        }
        wsum[lane] = z;
    }
    __syncthreads();
    int excl = x - v + (w > 0 ? wsum[w - 1] : 0);
    if (i < n) g_rowptr[i] = excl;
    if (t == 1023) g_bsum[blockIdx.x] = excl + v;
}

// scan of block sums + apply offsets + write cursor (single block)
__global__ __launch_bounds__(1024) void scan_p23(int nb, int n)
{
    __shared__ int boff[64];
    __shared__ int w0tot;
    int t = threadIdx.x;
    if (t < 64) {
        int v = (t < nb) ? g_bsum[t] : 0;
        int lane = t & 31;
        int x = v;
#pragma unroll
        for (int off = 1; off < 32; off <<= 1) {
            int y = __shfl_up_sync(0xffffffffu, x, off);
            if (lane >= off) x += y;
        }
        if (t == 31) w0tot = x;
        boff[t] = x - v;   // intra-warp exclusive
    }
    __syncthreads();
    if (t >= 32 && t < 64) boff[t] += w0tot;
    __syncthreads();
    if (t == 0)
        g_rowptr[n] = boff[nb - 1] + g_bsum[nb - 1];
    __syncthreads();
    for (int i = t; i < n; i += 1024) {
        int val = g_rowptr[i] + boff[i >> 10];
        g_rowptr[i] = val;
        g_cursor[i] = val;
    }
}

__global__ void scatter_kernel(const int* __restrict__ w, int E)
{
    int e = blockIdx.x * blockDim.x + threadIdx.x;
    if (e >= E) return;
    int is64 = g_idx64;
    int src = load_idx(w, e, is64);
    int dst = load_idx(w, E + e, is64);
    int pos = atomicAdd(&g_cursor[src], 1);
    g_col[pos] = dst;
}

// ---------------------------------------------------------------
// layer-1 attention + aggregation + ELU (warp per node, 4 heads, fp16 gather)
// ---------------------------------------------------------------
__global__ __launch_bounds__(256) void agg_heads(int N)
{
    int warp = (blockIdx.x * blockDim.x + threadIdx.x) >> 5;
    int lane = threadIdx.x & 31;
    if (warp >= N) return;

    int e0 = g_rowptr[warp];
    int e1 = g_rowptr[warp + 1];
    float4 s1v = *(const float4*)&g_s1h[warp * 4];
    float s1a[4] = {s1v.x, s1v.y, s1v.z, s1v.w};

    float m[4], l[4];
    float2 acc[4];
#pragma unroll
    for (int h = 0; h < 4; h++) {
        m[h] = -1e30f; l[h] = 0.f;
        acc[h] = make_float2(0.f, 0.f);
    }

    for (int e = e0; e < e1; e++) {
        int dst = g_col[e];
        float4 s2v = *(const float4*)&g_s2h[dst * 4];
        float s2a[4] = {s2v.x, s2v.y, s2v.z, s2v.w};
        const __half2* hr = g_H1h + (size_t)dst * 128;
#pragma unroll
        for (int h = 0; h < 4; h++) {
            float sv = s1a[h] + s2a[h];
            float sc = -(sv > 0.f ? sv : ALPHA * sv);
            float2 vf = __half22float2(hr[h * 32 + lane]);
            if (sc <= m[h]) {                 // warp-uniform branch
                float p = __expf(sc - m[h]);
                l[h] += p;
                acc[h].x += p * vf.x;
                acc[h].y += p * vf.y;
            } else {
                float s = __expf(m[h] - sc);
                l[h] = l[h] * s + 1.f;
                acc[h].x = acc[h].x * s + vf.x;
                acc[h].y = acc[h].y * s + vf.y;
                m[h] = sc;
            }
        }
    }

    float* orow = g_hcat + (size_t)warp * 256;
    bool has = (e1 > e0);
#pragma unroll
    for (int h = 0; h < 4; h++) {
        float va = 0.f, vb = 0.f;
        if (has) {
            float inv = 1.f / l[h];
            va = acc[h].x * inv;
            vb = acc[h].y * inv;
        }
        va = (va > 0.f) ? va : (__expf(va) - 1.f);   // ELU
        vb = (vb > 0.f) ? vb : (__expf(vb) - 1.f);
        *(float2*)(orow + h * 64 + 2 * lane) = make_float2(va, vb);
    }
}

// ---------------------------------------------------------------
// output-layer attention + aggregation (warp per node, dim 64, fp16 gather)
// ---------------------------------------------------------------
__global__ __launch_bounds__(256) void agg_out(float* __restrict__ out, int N)
{
    int warp = (blockIdx.x * blockDim.x + threadIdx.x) >> 5;
    int lane = threadIdx.x & 31;
    if (warp >= N) return;

    int e0 = g_rowptr[warp];
    int e1 = g_rowptr[warp + 1];
    float s1 = g_s1o[warp];

    float m = -1e30f, l = 0.f;
    float2 acc = make_float2(0.f, 0.f);
    for (int e = e0; e < e1; e++) {
        int dst = g_col[e];
        float sv = s1 + g_s2o[dst];
        float sc = -(sv > 0.f ? sv : ALPHA * sv);
        float2 vf = __half22float2(g_H2h[(size_t)dst * 32 + lane]);
        if (sc <= m) {
            float p = __expf(sc - m);
            l += p;
            acc.x += p * vf.x;
            acc.y += p * vf.y;
        } else {
            float s = __expf(m - sc);
            l = l * s + 1.f;
            acc.x = acc.x * s + vf.x;
            acc.y = acc.y * s + vf.y;
            m = sc;
        }
    }
    float va = 0.f, vb = 0.f;
    if (e1 > e0) {
        float inv = 1.f / l;
        va = acc.x * inv;
        vb = acc.y * inv;
    }
    *(float2*)(out + (size_t)warp * 64 + 2 * lane) = make_float2(va, vb);
}

// ---------------------------------------------------------------
extern "C" void kernel_launch(void* const* d_in, const int* in_sizes, int n_in,
                              void* d_out, int out_size)
{
    const float* x          = (const float*)d_in[0];
    const int*   ei_w       = (const int*)d_in[1];
    const float* W_heads    = (const float*)d_in[2];
    const float* attn_heads = (const float*)d_in[3];
    const float* W_out      = (const float*)d_in[4];
    const float* attn_out   = (const float*)d_in[5];
    float* out = (float*)d_out;

    int N = in_sizes[0] / 128;
    int E = in_sizes[1] / 2;

    int nodeWarpBlocks = (N + 7) / 8;
    int edgeBlocks = (E + 255) / 256;
    int scanBlocks = (N + 1023) / 1024;

    // lazy one-time stream/event setup (first call is NOT under capture)
    static cudaStream_t sSide = nullptr;
    static cudaEvent_t evFork = nullptr, evJoin = nullptr;
    if (!sSide) {
        cudaStreamCreateWithFlags(&sSide, cudaStreamNonBlocking);
        cudaEventCreateWithFlags(&evFork, cudaEventDisableTiming);
        cudaEventCreateWithFlags(&evJoin, cudaEventDisableTiming);
    }

    // fork: CSR chain on side stream, GEMM1 on main stream
    cudaEventRecord(evFork, 0);
    cudaStreamWaitEvent(sSide, evFork, 0);

    probe_dtype<<<1, 1, 0, sSide>>>(ei_w, E);
    hist_kernel<<<edgeBlocks, 256, 0, sSide>>>(ei_w, E);
    scan_p1<<<scanBlocks, 1024, 0, sSide>>>(N);
    scan_p23<<<1, 1024, 0, sSide>>>(scanBlocks, N);
    scatter_kernel<<<edgeBlocks, 256, 0, sSide>>>(ei_w, E);
    cudaEventRecord(evJoin, sSide);

    // GEMM1 (+ fused svec + fp16 mirror): 4 head tiles
    dim3 g1((N + 127) / 128, 4);
    tf32_gemm<<<g1, 256>>>(x, 128, W_heads, 128 * 64, attn_heads, /*layer=*/0, N, 128);

    // join
    cudaStreamWaitEvent(0, evJoin, 0);

    // layer-1 softmax+aggregate+ELU -> g_hcat
    agg_heads<<<nodeWarpBlocks, 256>>>(N);

    // GEMM2 (+ fused svec_out + fp16 mirror)
    dim3 g2((N + 127) / 128, 1);
    tf32_gemm<<<g2, 256>>>(nullptr, 256, W_out, 0, attn_out, /*layer=*/1, N, 256);

    // final aggregation
    agg_out<<<nodeWarpBlocks, 256>>>(out, N);
}

// round 5
// speedup vs baseline: 1.8886x; 1.2049x over previous
#include <cuda_runtime.h>
#include <cuda_fp16.h>
#include <math.h>

#define NMAX 50000
#define EMAX 800000
#define ALPHA 0.01f

// ---- static scratch (no allocations allowed) ----
__device__ __half2 g_H1h[(size_t)NMAX * 128]; // layer-1 features fp16, head-major (256 halves/row)
__device__ __half2 g_H2h[(size_t)NMAX * 32];  // layer-2 features fp16 (64 halves/row)
__device__ float g_hcat[(size_t)NMAX * 256];  // elu(attention output), layer-2 input (fp32)
__device__ float g_s1h[NMAX * 4];
__device__ float g_s2h[NMAX * 4];
__device__ float g_s1o[NMAX];
__device__ float g_s2o[NMAX];
__device__ int   g_count[NMAX];               // .bss zero-init; scan_p1 re-zeroes each call
__device__ int   g_rowptr[NMAX + 1];
__device__ int   g_cursor[NMAX];
__device__ int   g_col[EMAX];
__device__ int   g_bsum[64];

// ---------------------------------------------------------------
// Block-cooperative dtype probe: int64 little-endian node ids < 2^31
// have zero odd 32-bit words. One load per thread, block-wide AND.
// Must be called by ALL threads of a 256-thread block before any return.
// ---------------------------------------------------------------
__device__ __forceinline__ int block_probe_is64(const int* __restrict__ w, int E)
{
    int t = threadIdx.x;
    int nElem = (E < 128) ? E : 128;
    int ok = 1;
    if (t < nElem) ok = (w[2 * t + 1] == 0);
    return __syncthreads_and(ok);
}

__device__ __forceinline__ int load_idx(const int* __restrict__ w, int pos, int is64)
{
    return is64 ? w[2 * pos] : w[pos];
}

// ---------------------------------------------------------------
// tf32 tensor-core GEMM with fused epilogue:
//   - writes fp16 feature mirror (g_H1h / g_H2h)
//   - computes per-row attention score dots s1/s2 (quad shuffle reduce)
// layer 0: A(Mx128)=x, B=W_heads tile per blockIdx.y (4 heads)
// layer 1: A(Mx256)=g_hcat, B=W_out
// ---------------------------------------------------------------
__device__ __forceinline__ unsigned f2tf32(float f)
{
    unsigned u;
    asm("cvt.rna.tf32.f32 %0, %1;" : "=r"(u) : "f"(f));
    return u;
}

__device__ __forceinline__ void mma_tf32(
    float& d0, float& d1, float& d2, float& d3,
    unsigned a0, unsigned a1, unsigned a2, unsigned a3,
    unsigned b0, unsigned b1)
{
    asm volatile(
        "mma.sync.aligned.m16n8k8.row.col.f32.tf32.tf32.f32 "
        "{%0,%1,%2,%3}, {%4,%5,%6,%7}, {%8,%9}, {%0,%1,%2,%3};\n"
        : "+f"(d0), "+f"(d1), "+f"(d2), "+f"(d3)
        : "r"(a0), "r"(a1), "r"(a2), "r"(a3), "r"(b0), "r"(b1));
}

__global__ __launch_bounds__(256) void tf32_gemm(
    const float* __restrict__ A, int lda,
    const float* __restrict__ B0, int bStride,
    const float* __restrict__ attn, int layer, int M, int K)
{
    __shared__ unsigned As[2][128][20];   // double-buffered 16-k chunks of A
    __shared__ unsigned Bs[128][72];      // full 128-k chunk of B

    const float* Ap = A ? A : g_hcat;
    int head = blockIdx.y;
    const float* B = B0 + (size_t)head * bStride;
    int row0 = blockIdx.x * 128;

    int tid = threadIdx.x;
    int lane = tid & 31, w = tid >> 5;
    int gid = lane >> 2, qid = lane & 3;

    float acc[8][4];
#pragma unroll
    for (int i = 0; i < 8; i++)
#pragma unroll
        for (int j = 0; j < 4; j++) acc[i][j] = 0.f;

    // A chunk stager: loads 128 rows x 16 k at column offset koff into As[buf]
    auto stageA = [&](int koff, int buf) {
#pragma unroll
        for (int i = 0; i < 2; i++) {
            int u = tid + i * 256;
            int ar = u >> 2, c4 = (u & 3) * 4;
            float4 av = make_float4(0.f, 0.f, 0.f, 0.f);
            if (row0 + ar < M)
                av = *(const float4*)(Ap + (size_t)(row0 + ar) * lda + koff + c4);
            As[buf][ar][c4 + 0] = f2tf32(av.x);
            As[buf][ar][c4 + 1] = f2tf32(av.y);
            As[buf][ar][c4 + 2] = f2tf32(av.z);
            As[buf][ar][c4 + 3] = f2tf32(av.w);
        }
    };

    for (int kc = 0; kc < K; kc += 128) {
        if (kc) __syncthreads();                // all compute done with old Bs
        for (int i = tid; i < 128 * 16; i += 256) {
            int br = i >> 4, bc4 = (i & 15) * 4;
            float4 bv = *(const float4*)(B + (size_t)(kc + br) * 64 + bc4);
            Bs[br][bc4 + 0] = f2tf32(bv.x);
            Bs[br][bc4 + 1] = f2tf32(bv.y);
            Bs[br][bc4 + 2] = f2tf32(bv.z);
            Bs[br][bc4 + 3] = f2tf32(bv.w);
        }
        stageA(kc, 0);
        __syncthreads();

        for (int ks = 0; ks < 128; ks += 16) {
            int buf = (ks >> 4) & 1;
            if (ks + 16 < 128) stageA(kc + ks + 16, buf ^ 1);

#pragma unroll
            for (int k8 = 0; k8 < 16; k8 += 8) {
                unsigned a0 = As[buf][w * 16 + gid][k8 + qid];
                unsigned a1 = As[buf][w * 16 + gid + 8][k8 + qid];
                unsigned a2 = As[buf][w * 16 + gid][k8 + qid + 4];
                unsigned a3 = As[buf][w * 16 + gid + 8][k8 + qid + 4];
                int krow = ks + k8 + qid;
#pragma unroll
                for (int n0 = 0; n0 < 8; n0++) {
                    unsigned b0 = Bs[krow][n0 * 8 + gid];
                    unsigned b1 = Bs[krow + 4][n0 * 8 + gid];
                    mma_tf32(acc[n0][0], acc[n0][1], acc[n0][2], acc[n0][3],
                             a0, a1, a2, a3, b0, b1);
                }
            }
            __syncthreads();
        }
    }

    // ---- fused epilogue ----
    __half2* Hh2;
    int ldH2, colBase2, sStride, sOff;
    float *s1g, *s2g;
    const float* a1;
    if (layer == 0) {
        Hh2 = g_H1h; ldH2 = 128; colBase2 = head * 32;
        sStride = 4; sOff = head; s1g = g_s1h; s2g = g_s2h;
        a1 = attn + head * 128;
    } else {
        Hh2 = g_H2h; ldH2 = 32; colBase2 = 0;
        sStride = 1; sOff = 0; s1g = g_s1o; s2g = g_s2o;
        a1 = attn;
    }
    const float* a2v = a1 + 64;

    int r1 = row0 + w * 16 + gid;
    int r2 = r1 + 8;

    float p1a = 0.f, p2a = 0.f, p1b = 0.f, p2b = 0.f;
#pragma unroll
    for (int n0 = 0; n0 < 8; n0++) {
        int c0 = n0 * 8 + 2 * qid;
        float w10 = __ldg(a1 + c0), w11 = __ldg(a1 + c0 + 1);
        float w20 = __ldg(a2v + c0), w21 = __ldg(a2v + c0 + 1);
        p1a += acc[n0][0] * w10 + acc[n0][1] * w11;
        p2a += acc[n0][0] * w20 + acc[n0][1] * w21;
        p1b += acc[n0][2] * w10 + acc[n0][3] * w11;
        p2b += acc[n0][2] * w20 + acc[n0][3] * w21;
    }
#pragma unroll
    for (int off = 1; off < 4; off <<= 1) {
        p1a += __shfl_xor_sync(0xffffffffu, p1a, off);
        p2a += __shfl_xor_sync(0xffffffffu, p2a, off);
        p1b += __shfl_xor_sync(0xffffffffu, p1b, off);
        p2b += __shfl_xor_sync(0xffffffffu, p2b, off);
    }
    if (qid == 0) {
        if (r1 < M) { s1g[r1 * sStride + sOff] = p1a; s2g[r1 * sStride + sOff] = p2a; }
        if (r2 < M) { s1g[r2 * sStride + sOff] = p1b; s2g[r2 * sStride + sOff] = p2b; }
    }

#pragma unroll
    for (int n0 = 0; n0 < 8; n0++) {
        int cc = colBase2 + n0 * 4 + qid;
        if (r1 < M)
            Hh2[(size_t)r1 * ldH2 + cc] = __floats2half2_rn(acc[n0][0], acc[n0][1]);
        if (r2 < M)
            Hh2[(size_t)r2 * ldH2 + cc] = __floats2half2_rn(acc[n0][2], acc[n0][3]);
    }
}

// ---------------------------------------------------------------
// CSR build
// ---------------------------------------------------------------
__global__ __launch_bounds__(256) void hist_kernel(const int* __restrict__ w, int E)
{
    int is64 = block_probe_is64(w, E);
    int e = blockIdx.x * blockDim.x + threadIdx.x;
    if (e >= E) return;
    atomicAdd(&g_count[load_idx(w, e, is64)], 1);
}

__global__ __launch_bounds__(1024) void scan_p1(int n)
{
    __shared__ int wsum[32];
    int t = threadIdx.x;
    int i = blockIdx.x * 1024 + t;
    int v = (i < n) ? g_count[i] : 0;
    if (i < n) g_count[i] = 0;            // self-clear for next call
    int lane = t & 31, w = t >> 5;

    int x = v;
#pragma unroll
    for (int off = 1; off < 32; off <<= 1) {
        int y = __shfl_up_sync(0xffffffffu, x, off);
        if (lane >= off) x += y;
    }
    if (lane == 31) wsum[w] = x;
    __syncthreads();
    if (w == 0) {
        int z = wsum[lane];
#pragma unroll
        for (int off = 1; off < 32; off <<= 1) {
            int y = __shfl_up_sync(0xffffffffu, z, off);
            if (lane >= off) z += y;
        }
        wsum[lane] = z;
    }
    __syncthreads();
    int excl = x - v + (w > 0 ? wsum[w - 1] : 0);
    if (i < n) g_rowptr[i] = excl;
    if (t == 1023) g_bsum[blockIdx.x] = excl + v;
}

// grid-wide apply: each block locally scans the <=64 block sums, then applies.
__global__ __launch_bounds__(1024) void scan_p3(int nb, int n)
{
    __shared__ int boff[64];
    int t = threadIdx.x;
    if (t < 64) {
        int v = (t < nb) ? g_bsum[t] : 0;
        int lane = t & 31;
        int x = v;
#pragma unroll
        for (int off = 1; off < 32; off <<= 1) {
            int y = __shfl_up_sync(0xffffffffu, x, off);
            if (lane >= off) x += y;
        }
        boff[t] = x - v;     // intra-warp exclusive
    }
    __syncthreads();
    if (t >= 32 && t < 64)
        boff[t] += boff[31] + g_bsum[31];   // add warp-0 total (nb<=64 and nb>=32 here; if nb<32 the adds hit unused slots)
    __syncthreads();

    int i = blockIdx.x * 1024 + t;
    if (i < n) {
        int val = g_rowptr[i] + boff[blockIdx.x];
        g_rowptr[i] = val;
        g_cursor[i] = val;
    }
    if (blockIdx.x == 0 && t == 0)
        g_rowptr[n] = boff[nb - 1] + g_bsum[nb - 1];
}

__global__ __launch_bounds__(256) void scatter_kernel(const int* __restrict__ w, int E)
{
    int is64 = block_probe_is64(w, E);
    int e = blockIdx.x * blockDim.x + threadIdx.x;
    if (e >= E) return;
    int src = load_idx(w, e, is64);
    int dst = load_idx(w, E + e, is64);
    int pos = atomicAdd(&g_cursor[src], 1);
    g_col[pos] = dst;
}

// ---------------------------------------------------------------
// layer-1 attention + aggregation + ELU (warp per node, 4 heads, fp16 gather)
// exact two-pass softmax; one exp per edge per quad-lane (head = lane&3)
// ---------------------------------------------------------------
__device__ __forceinline__ float sel4(float4 v, int q)
{
    float r = v.x;
    r = (q == 1) ? v.y : r;
    r = (q == 2) ? v.z : r;
    r = (q == 3) ? v.w : r;
    return r;
}

__global__ __launch_bounds__(256) void agg_heads(int N)
{
    int warp = (blockIdx.x * blockDim.x + threadIdx.x) >> 5;
    int lane = threadIdx.x & 31;
    if (warp >= N) return;

    int e0 = g_rowptr[warp];
    int e1 = g_rowptr[warp + 1];
    int hq = lane & 3;                 // this lane's head for score work
    float4 s1v = *(const float4*)&g_s1h[warp * 4];
    float s1q = sel4(s1v, hq);

    // ---- pass 1: per-head max (no exp) ----
    float mloc = -1e30f;
    for (int e = e0; e < e1; e++) {
        int dst = g_col[e];
        float4 s2v = *(const float4*)&g_s2h[dst * 4];
        float sv = s1q + sel4(s2v, hq);
        float sc = -(sv > 0.f ? sv : ALPHA * sv);
        mloc = fmaxf(mloc, sc);
    }

    // ---- pass 2: branchless accumulate ----
    float lloc = 0.f;
    float2 acc[4];
#pragma unroll
    for (int h = 0; h < 4; h++) acc[h] = make_float2(0.f, 0.f);

    const __half2* H = g_H1h;
    for (int e = e0; e < e1; e++) {
        int dst = g_col[e];
        float4 s2v = *(const float4*)&g_s2h[dst * 4];
        float sv = s1q + sel4(s2v, hq);
        float sc = -(sv > 0.f ? sv : ALPHA * sv);
        float p = __expf(sc - mloc);   // own head only
        lloc += p;
        float p0 = __shfl_sync(0xffffffffu, p, 0, 4);
        float p1 = __shfl_sync(0xffffffffu, p, 1, 4);
        float p2 = __shfl_sync(0xffffffffu, p, 2, 4);
        float p3 = __shfl_sync(0xffffffffu, p, 3, 4);
        const __half2* hr = H + (size_t)dst * 128;
        float2 v0 = __half22float2(hr[lane]);
        float2 v1 = __half22float2(hr[32 + lane]);
        float2 v2 = __half22float2(hr[64 + lane]);
        float2 v3 = __half22float2(hr[96 + lane]);
        acc[0].x += p0 * v0.x; acc[0].y += p0 * v0.y;
        acc[1].x += p1 * v1.x; acc[1].y += p1 * v1.y;
        acc[2].x += p2 * v2.x; acc[2].y += p2 * v2.y;
        acc[3].x += p3 * v3.x; acc[3].y += p3 * v3.y;
    }

    float* orow = g_hcat + (size_t)warp * 256;
    bool has = (e1 > e0);
#pragma unroll
    for (int h = 0; h < 4; h++) {
        float lh = __shfl_sync(0xffffffffu, lloc, h, 4);
        float va = 0.f, vb = 0.f;
        if (has) {
            float inv = 1.f / lh;
            va = acc[h].x * inv;
            vb = acc[h].y * inv;
        }
        va = (va > 0.f) ? va : (__expf(va) - 1.f);   // ELU
        vb = (vb > 0.f) ? vb : (__expf(vb) - 1.f);
        *(float2*)(orow + h * 64 + 2 * lane) = make_float2(va, vb);
    }
}

// ---------------------------------------------------------------
// output-layer attention + aggregation (warp per node, dim 64, fp16 gather)
// exact two-pass softmax
// ---------------------------------------------------------------
__global__ __launch_bounds__(256) void agg_out(float* __restrict__ out, int N)
{
    int warp = (blockIdx.x * blockDim.x + threadIdx.x) >> 5;
    int lane = threadIdx.x & 31;
    if (warp >= N) return;

    int e0 = g_rowptr[warp];
    int e1 = g_rowptr[warp + 1];
    float s1 = g_s1o[warp];

    float m = -1e30f;
    for (int e = e0; e < e1; e++) {
        int dst = g_col[e];
        float sv = s1 + g_s2o[dst];
        float sc = -(sv > 0.f ? sv : ALPHA * sv);
        m = fmaxf(m, sc);
    }

    float l = 0.f;
    float2 acc = make_float2(0.f, 0.f);
    for (int e = e0; e < e1; e++) {
        int dst = g_col[e];
        float sv = s1 + g_s2o[dst];
        float sc = -(sv > 0.f ? sv : ALPHA * sv);
        float p = __expf(sc - m);
        l += p;
        float2 vf = __half22float2(g_H2h[(size_t)dst * 32 + lane]);
        acc.x += p * vf.x;
        acc.y += p * vf.y;
    }

    float va = 0.f, vb = 0.f;
    if (e1 > e0) {
        float inv = 1.f / l;
        va = acc.x * inv;
        vb = acc.y * inv;
    }
    *(float2*)(out + (size_t)warp * 64 + 2 * lane) = make_float2(va, vb);
}

// ---------------------------------------------------------------
extern "C" void kernel_launch(void* const* d_in, const int* in_sizes, int n_in,
                              void* d_out, int out_size)
{
    const float* x          = (const float*)d_in[0];
    const int*   ei_w       = (const int*)d_in[1];
    const float* W_heads    = (const float*)d_in[2];
    const float* attn_heads = (const float*)d_in[3];
    const float* W_out      = (const float*)d_in[4];
    const float* attn_out   = (const float*)d_in[5];
    float* out = (float*)d_out;

    int N = in_sizes[0] / 128;
    int E = in_sizes[1] / 2;

    int nodeWarpBlocks = (N + 7) / 8;
    int edgeBlocks = (E + 255) / 256;
    int scanBlocks = (N + 1023) / 1024;

    // lazy one-time stream/event setup (first call is NOT under capture)
    static cudaStream_t sSide = nullptr;
    static cudaEvent_t evFork = nullptr, evJoin = nullptr;
    if (!sSide) {
        cudaStreamCreateWithFlags(&sSide, cudaStreamNonBlocking);
        cudaEventCreateWithFlags(&evFork, cudaEventDisableTiming);
        cudaEventCreateWithFlags(&evJoin, cudaEventDisableTiming);
    }

    // fork: CSR chain on side stream, GEMM1 on main stream
    cudaEventRecord(evFork, 0);
    cudaStreamWaitEvent(sSide, evFork, 0);

    hist_kernel<<<edgeBlocks, 256, 0, sSide>>>(ei_w, E);   // launch 1
    scan_p1<<<scanBlocks, 1024, 0, sSide>>>(N);            // launch 2
    scan_p3<<<scanBlocks, 1024, 0, sSide>>>(scanBlocks, N);// launch 3

    // GEMM1 (+ fused svec + fp16 mirror): 4 head tiles  — launch 4 (ncu slot)
    dim3 g1((N + 127) / 128, 4);
    tf32_gemm<<<g1, 256>>>(x, 128, W_heads, 128 * 64, attn_heads, /*layer=*/0, N, 128);

    scatter_kernel<<<edgeBlocks, 256, 0, sSide>>>(ei_w, E);// launch 5
    cudaEventRecord(evJoin, sSide);

    // join
    cudaStreamWaitEvent(0, evJoin, 0);

    // layer-1 softmax+aggregate+ELU -> g_hcat
    agg_heads<<<nodeWarpBlocks, 256>>>(N);

    // GEMM2 (+ fused svec_out + fp16 mirror)
    dim3 g2((N + 127) / 128, 1);
    tf32_gemm<<<g2, 256>>>(nullptr, 256, W_out, 0, attn_out, /*layer=*/1, N, 256);

    // final aggregation
    agg_out<<<nodeWarpBlocks, 256>>>(out, N);
}

// round 6
// speedup vs baseline: 2.3433x; 1.2408x over previous
#include <cuda_runtime.h>
#include <cuda_fp16.h>
#include <math.h>

#define NMAX 50000
#define EMAX 800000
#define ALPHA 0.01f

// ---- static scratch (no allocations allowed) ----
__device__ __half2 g_H1h[(size_t)NMAX * 128]; // layer-1 features fp16, head-major (256 halves/row)
__device__ __half2 g_H2h[(size_t)NMAX * 32];  // layer-2 features fp16 (64 halves/row)
__device__ float g_hcat[(size_t)NMAX * 256];  // elu(attention output), layer-2 input (fp32)
__device__ float g_s1h[NMAX * 4];
__device__ float g_s2h[NMAX * 4];
__device__ float g_s1o[NMAX];
__device__ float g_s2o[NMAX];
__device__ int   g_count[NMAX];               // .bss zero-init; scan_p1 re-zeroes each call
__device__ int   g_rowptr[NMAX + 1];
__device__ int   g_cursor[NMAX];
__device__ int   g_col[EMAX];
__device__ int   g_bsum[64];

// ---------------------------------------------------------------
__device__ __forceinline__ int block_probe_is64(const int* __restrict__ w, int E)
{
    int t = threadIdx.x;
    int nElem = (E < 128) ? E : 128;
    int ok = 1;
    if (t < nElem) ok = (w[2 * t + 1] == 0);
    return __syncthreads_and(ok);
}

__device__ __forceinline__ int load_idx(const int* __restrict__ w, int pos, int is64)
{
    return is64 ? w[2 * pos] : w[pos];
}

// ---------------------------------------------------------------
// tf32 tensor-core GEMM, 256-row blocks, 32 rows x 64 cols per warp.
// Fused epilogue: fp16 mirror + attention score dots.
// ---------------------------------------------------------------
__device__ __forceinline__ unsigned f2tf32(float f)
{
    unsigned u;
    asm("cvt.rna.tf32.f32 %0, %1;" : "=r"(u) : "f"(f));
    return u;
}

__device__ __forceinline__ void mma_tf32(
    float* d,
    unsigned a0, unsigned a1, unsigned a2, unsigned a3,
    unsigned b0, unsigned b1)
{
    asm volatile(
        "mma.sync.aligned.m16n8k8.row.col.f32.tf32.tf32.f32 "
        "{%0,%1,%2,%3}, {%4,%5,%6,%7}, {%8,%9}, {%0,%1,%2,%3};\n"
        : "+f"(d[0]), "+f"(d[1]), "+f"(d[2]), "+f"(d[3])
        : "r"(a0), "r"(a1), "r"(a2), "r"(a3), "r"(b0), "r"(b1));
}

#define GEMM_SMEM (128*72*4 + 2*256*20*4)   // Bs + double-buffered As = 77824 B

__global__ __launch_bounds__(256, 2) void tf32_gemm(
    const float* __restrict__ A, int lda,
    const float* __restrict__ B0, int bStride,
    const float* __restrict__ attn, int layer, int M, int K)
{
    extern __shared__ unsigned dsm[];
    unsigned (*Bs)[72] = (unsigned(*)[72])dsm;              // [128][72]
    unsigned (*As)[20] = (unsigned(*)[20])(dsm + 128 * 72); // [2*256][20]

    const float* Ap = A ? A : g_hcat;
    int head = blockIdx.y;
    const float* B = B0 + (size_t)head * bStride;
    int row0 = blockIdx.x * 256;

    int tid = threadIdx.x;
    int lane = tid & 31, w = tid >> 5;
    int gid = lane >> 2, qid = lane & 3;

    float acc0[8][4], acc1[8][4];
#pragma unroll
    for (int i = 0; i < 8; i++)
#pragma unroll
        for (int j = 0; j < 4; j++) { acc0[i][j] = 0.f; acc1[i][j] = 0.f; }

    auto stageA = [&](int koff, int buf) {
#pragma unroll
        for (int i = 0; i < 4; i++) {
            int u = tid + i * 256;
            int ar = u >> 2, c4 = (u & 3) * 4;
            float4 av = make_float4(0.f, 0.f, 0.f, 0.f);
            if (row0 + ar < M)
                av = *(const float4*)(Ap + (size_t)(row0 + ar) * lda + koff + c4);
            unsigned* dstp = &As[(buf << 8) + ar][c4];
            dstp[0] = f2tf32(av.x);
            dstp[1] = f2tf32(av.y);
            dstp[2] = f2tf32(av.z);
            dstp[3] = f2tf32(av.w);
        }
    };

    for (int kc = 0; kc < K; kc += 128) {
        if (kc) __syncthreads();
        for (int i = tid; i < 128 * 16; i += 256) {
            int br = i >> 4, bc4 = (i & 15) * 4;
            float4 bv = *(const float4*)(B + (size_t)(kc + br) * 64 + bc4);
            Bs[br][bc4 + 0] = f2tf32(bv.x);
            Bs[br][bc4 + 1] = f2tf32(bv.y);
            Bs[br][bc4 + 2] = f2tf32(bv.z);
            Bs[br][bc4 + 3] = f2tf32(bv.w);
        }
        stageA(kc, 0);
        __syncthreads();

        for (int ks = 0; ks < 128; ks += 16) {
            int buf = (ks >> 4) & 1;
            if (ks + 16 < 128) stageA(kc + ks + 16, buf ^ 1);

#pragma unroll
            for (int k8 = 0; k8 < 16; k8 += 8) {
                int rb = (buf << 8) + w * 32 + gid;
                unsigned a00 = As[rb][k8 + qid];
                unsigned a01 = As[rb + 8][k8 + qid];
                unsigned a02 = As[rb][k8 + qid + 4];
                unsigned a03 = As[rb + 8][k8 + qid + 4];
                unsigned a10 = As[rb + 16][k8 + qid];
                unsigned a11 = As[rb + 24][k8 + qid];
                unsigned a12 = As[rb + 16][k8 + qid + 4];
                unsigned a13 = As[rb + 24][k8 + qid + 4];
                int krow = ks + k8 + qid;
#pragma unroll
                for (int n0 = 0; n0 < 8; n0++) {
                    unsigned b0 = Bs[krow][n0 * 8 + gid];
                    unsigned b1 = Bs[krow + 4][n0 * 8 + gid];
                    mma_tf32(acc0[n0], a00, a01, a02, a03, b0, b1);
                    mma_tf32(acc1[n0], a10, a11, a12, a13, b0, b1);
                }
            }
            __syncthreads();
        }
    }

    // ---- fused epilogue ----
    __half2* Hh2;
    int ldH2, colBase2, sStride, sOff;
    float *s1g, *s2g;
    const float* a1;
    if (layer == 0) {
        Hh2 = g_H1h; ldH2 = 128; colBase2 = head * 32;
        sStride = 4; sOff = head; s1g = g_s1h; s2g = g_s2h;
        a1 = attn + head * 128;
    } else {
        Hh2 = g_H2h; ldH2 = 32; colBase2 = 0;
        sStride = 1; sOff = 0; s1g = g_s1o; s2g = g_s2o;
        a1 = attn;
    }
    const float* a2v = a1 + 64;

    int rb = row0 + w * 32 + gid;
    int rows[4] = {rb, rb + 8, rb + 16, rb + 24};

    float d1[4] = {0.f, 0.f, 0.f, 0.f};
    float d2[4] = {0.f, 0.f, 0.f, 0.f};
#pragma unroll
    for (int n0 = 0; n0 < 8; n0++) {
        int c0 = n0 * 8 + 2 * qid;
        float w10 = __ldg(a1 + c0), w11 = __ldg(a1 + c0 + 1);
        float w20 = __ldg(a2v + c0), w21 = __ldg(a2v + c0 + 1);
        d1[0] += acc0[n0][0] * w10 + acc0[n0][1] * w11;
        d2[0] += acc0[n0][0] * w20 + acc0[n0][1] * w21;
        d1[1] += acc0[n0][2] * w10 + acc0[n0][3] * w11;
        d2[1] += acc0[n0][2] * w20 + acc0[n0][3] * w21;
        d1[2] += acc1[n0][0] * w10 + acc1[n0][1] * w11;
        d2[2] += acc1[n0][0] * w20 + acc1[n0][1] * w21;
        d1[3] += acc1[n0][2] * w10 + acc1[n0][3] * w11;
        d2[3] += acc1[n0][2] * w20 + acc1[n0][3] * w21;
    }
#pragma unroll
    for (int f = 0; f < 4; f++) {
#pragma unroll
        for (int off = 1; off < 4; off <<= 1) {
            d1[f] += __shfl_xor_sync(0xffffffffu, d1[f], off);
            d2[f] += __shfl_xor_sync(0xffffffffu, d2[f], off);
        }
    }
    if (qid == 0) {
#pragma unroll
        for (int f = 0; f < 4; f++) {
            if (rows[f] < M) {
                s1g[rows[f] * sStride + sOff] = d1[f];
                s2g[rows[f] * sStride + sOff] = d2[f];
            }
        }
    }

#pragma unroll
    for (int n0 = 0; n0 < 8; n0++) {
        int cc = colBase2 + n0 * 4 + qid;
        if (rows[0] < M)
            Hh2[(size_t)rows[0] * ldH2 + cc] = __floats2half2_rn(acc0[n0][0], acc0[n0][1]);
        if (rows[1] < M)
            Hh2[(size_t)rows[1] * ldH2 + cc] = __floats2half2_rn(acc0[n0][2], acc0[n0][3]);
        if (rows[2] < M)
            Hh2[(size_t)rows[2] * ldH2 + cc] = __floats2half2_rn(acc1[n0][0], acc1[n0][1]);
        if (rows[3] < M)
            Hh2[(size_t)rows[3] * ldH2 + cc] = __floats2half2_rn(acc1[n0][2], acc1[n0][3]);
    }
}

// ---------------------------------------------------------------
// CSR build
// ---------------------------------------------------------------
__global__ __launch_bounds__(256) void hist_kernel(const int* __restrict__ w, int E)
{
    int is64 = block_probe_is64(w, E);
    int e = blockIdx.x * blockDim.x + threadIdx.x;
    if (e >= E) return;
    atomicAdd(&g_count[load_idx(w, e, is64)], 1);
}

__global__ __launch_bounds__(1024) void scan_p1(int n)
{
    __shared__ int wsum[32];
    int t = threadIdx.x;
    int i = blockIdx.x * 1024 + t;
    int v = (i < n) ? g_count[i] : 0;
    if (i < n) g_count[i] = 0;            // self-clear for next call
    int lane = t & 31, w = t >> 5;

    int x = v;
#pragma unroll
    for (int off = 1; off < 32; off <<= 1) {
        int y = __shfl_up_sync(0xffffffffu, x, off);
        if (lane >= off) x += y;
    }
    if (lane == 31) wsum[w] = x;
    __syncthreads();
    if (w == 0) {
        int z = wsum[lane];
#pragma unroll
        for (int off = 1; off < 32; off <<= 1) {
            int y = __shfl_up_sync(0xffffffffu, z, off);
            if (lane >= off) z += y;
        }
        wsum[lane] = z;
    }
    __syncthreads();
    int excl = x - v + (w > 0 ? wsum[w - 1] : 0);
    if (i < n) g_rowptr[i] = excl;
    if (t == 1023) g_bsum[blockIdx.x] = excl + v;
}

__global__ __launch_bounds__(1024) void scan_p3(int nb, int n)
{
    __shared__ int boff[64];
    int t = threadIdx.x;
    if (t < 64) {
        int v = (t < nb) ? g_bsum[t] : 0;
        int lane = t & 31;
        int x = v;
#pragma unroll
        for (int off = 1; off < 32; off <<= 1) {
            int y = __shfl_up_sync(0xffffffffu, x, off);
            if (lane >= off) x += y;
        }
        boff[t] = x - v;
    }
    __syncthreads();
    if (t >= 32 && t < 64)
        boff[t] += boff[31] + g_bsum[31];
    __syncthreads();

    int i = blockIdx.x * 1024 + t;
    if (i < n) {
        int val = g_rowptr[i] + boff[blockIdx.x];
        g_rowptr[i] = val;
        g_cursor[i] = val;
    }
    if (blockIdx.x == 0 && t == 0)
        g_rowptr[n] = boff[nb - 1] + g_bsum[nb - 1];
}

__global__ __launch_bounds__(256) void scatter_kernel(const int* __restrict__ w, int E)
{
    int is64 = block_probe_is64(w, E);
    int e = blockIdx.x * blockDim.x + threadIdx.x;
    if (e >= E) return;
    int src = load_idx(w, e, is64);
    int dst = load_idx(w, E + e, is64);
    int pos = atomicAdd(&g_cursor[src], 1);
    g_col[pos] = dst;
}

// ---------------------------------------------------------------
// layer-1 attention + aggregation + ELU (warp per node, 4 heads)
// single-pass softmax (no max subtraction; scores bounded), col prefetch
// ---------------------------------------------------------------
__device__ __forceinline__ float sel4(float4 v, int q)
{
    float r = v.x;
    r = (q == 1) ? v.y : r;
    r = (q == 2) ? v.z : r;
    r = (q == 3) ? v.w : r;
    return r;
}

__global__ __launch_bounds__(256) void agg_heads(int N)
{
    int warp = (blockIdx.x * blockDim.x + threadIdx.x) >> 5;
    int lane = threadIdx.x & 31;
    if (warp >= N) return;

    int e0 = g_rowptr[warp];
    int e1 = g_rowptr[warp + 1];
    int hq = lane & 3;
    float4 s1v = *(const float4*)&g_s1h[warp * 4];
    float s1q = sel4(s1v, hq);

    float lloc = 0.f;
    float2 acc[4];
#pragma unroll
    for (int h = 0; h < 4; h++) acc[h] = make_float2(0.f, 0.f);

    int dst = (e0 < e1) ? g_col[e0] : 0;
    for (int e = e0; e < e1; e++) {
        int dstn = (e + 1 < e1) ? g_col[e + 1] : 0;
        float4 s2v = *(const float4*)&g_s2h[dst * 4];
        const __half2* hr = g_H1h + (size_t)dst * 128;
        float2 v0 = __half22float2(hr[lane]);
        float2 v1 = __half22float2(hr[32 + lane]);
        float2 v2 = __half22float2(hr[64 + lane]);
        float2 v3 = __half22float2(hr[96 + lane]);

        float sv = s1q + sel4(s2v, hq);
        float sc = -(sv > 0.f ? sv : ALPHA * sv);
        float p = __expf(sc);              // own head only
        lloc += p;
        float p0 = __shfl_sync(0xffffffffu, p, 0, 4);
        float p1 = __shfl_sync(0xffffffffu, p, 1, 4);
        float p2 = __shfl_sync(0xffffffffu, p, 2, 4);
        float p3 = __shfl_sync(0xffffffffu, p, 3, 4);

        acc[0].x += p0 * v0.x; acc[0].y += p0 * v0.y;
        acc[1].x += p1 * v1.x; acc[1].y += p1 * v1.y;
        acc[2].x += p2 * v2.x; acc[2].y += p2 * v2.y;
        acc[3].x += p3 * v3.x; acc[3].y += p3 * v3.y;
        dst = dstn;
    }

    float* orow = g_hcat + (size_t)warp * 256;
    bool has = (e1 > e0);
#pragma unroll
    for (int h = 0; h < 4; h++) {
        float lh = __shfl_sync(0xffffffffu, lloc, h, 4);
        float va = 0.f, vb = 0.f;
        if (has) {
            float inv = 1.f / lh;
            va = acc[h].x * inv;
            vb = acc[h].y * inv;
        }
        va = (va > 0.f) ? va : (__expf(va) - 1.f);   // ELU
        vb = (vb > 0.f) ? vb : (__expf(vb) - 1.f);
        *(float2*)(orow + h * 64 + 2 * lane) = make_float2(va, vb);
    }
}

// ---------------------------------------------------------------
// output-layer aggregation (warp per node, dim 64), single-pass softmax
// ---------------------------------------------------------------
__global__ __launch_bounds__(256) void agg_out(float* __restrict__ out, int N)
{
    int warp = (blockIdx.x * blockDim.x + threadIdx.x) >> 5;
    int lane = threadIdx.x & 31;
    if (warp >= N) return;

    int e0 = g_rowptr[warp];
    int e1 = g_rowptr[warp + 1];
    float s1 = g_s1o[warp];

    float l = 0.f;
    float2 acc = make_float2(0.f, 0.f);
    int dst = (e0 < e1) ? g_col[e0] : 0;
    for (int e = e0; e < e1; e++) {
        int dstn = (e + 1 < e1) ? g_col[e + 1] : 0;
        float s2 = g_s2o[dst];
        float2 vf = __half22float2(g_H2h[(size_t)dst * 32 + lane]);
        float sv = s1 + s2;
        float sc = -(sv > 0.f ? sv : ALPHA * sv);
        float p = __expf(sc);
        l += p;
        acc.x += p * vf.x;
        acc.y += p * vf.y;
        dst = dstn;
    }

    float va = 0.f, vb = 0.f;
    if (e1 > e0) {
        float inv = 1.f / l;
        va = acc.x * inv;
        vb = acc.y * inv;
    }
    *(float2*)(out + (size_t)warp * 64 + 2 * lane) = make_float2(va, vb);
}

// ---------------------------------------------------------------
extern "C" void kernel_launch(void* const* d_in, const int* in_sizes, int n_in,
                              void* d_out, int out_size)
{
    const float* x          = (const float*)d_in[0];
    const int*   ei_w       = (const int*)d_in[1];
    const float* W_heads    = (const float*)d_in[2];
    const float* attn_heads = (const float*)d_in[3];
    const float* W_out      = (const float*)d_in[4];
    const float* attn_out   = (const float*)d_in[5];
    float* out = (float*)d_out;

    int N = in_sizes[0] / 128;
    int E = in_sizes[1] / 2;

    int nodeWarpBlocks = (N + 7) / 8;
    int edgeBlocks = (E + 255) / 256;
    int scanBlocks = (N + 1023) / 1024;

    // one-time setup (first call is NOT under capture)
    static cudaStream_t sSide = nullptr;
    static cudaEvent_t evFork = nullptr, evJoin = nullptr;
    if (!sSide) {
        cudaStreamCreateWithFlags(&sSide, cudaStreamNonBlocking);
        cudaEventCreateWithFlags(&evFork, cudaEventDisableTiming);
        cudaEventCreateWithFlags(&evJoin, cudaEventDisableTiming);
        cudaFuncSetAttribute(tf32_gemm, cudaFuncAttributeMaxDynamicSharedMemorySize, GEMM_SMEM);
    }

    // fork: CSR chain on side stream, GEMM1 on main stream
    cudaEventRecord(evFork, 0);
    cudaStreamWaitEvent(sSide, evFork, 0);

    hist_kernel<<<edgeBlocks, 256, 0, sSide>>>(ei_w, E);    // launch 1
    scan_p1<<<scanBlocks, 1024, 0, sSide>>>(N);             // launch 2
    scan_p3<<<scanBlocks, 1024, 0, sSide>>>(scanBlocks, N); // launch 3

    // GEMM1 (+ fused svec + fp16 mirror) — launch 4 (ncu slot)
    dim3 g1((N + 255) / 256, 4);
    tf32_gemm<<<g1, 256, GEMM_SMEM>>>(x, 128, W_heads, 128 * 64, attn_heads, 0, N, 128);

    scatter_kernel<<<edgeBlocks, 256, 0, sSide>>>(ei_w, E); // launch 5
    cudaEventRecord(evJoin, sSide);

    cudaStreamWaitEvent(0, evJoin, 0);

    // layer-1 softmax+aggregate+ELU -> g_hcat
    agg_heads<<<nodeWarpBlocks, 256>>>(N);

    // GEMM2 (+ fused svec_out + fp16 mirror)
    dim3 g2((N + 255) / 256, 1);
    tf32_gemm<<<g2, 256, GEMM_SMEM>>>(nullptr, 256, W_out, 0, attn_out, 1, N, 256);

    // final aggregation
    agg_out<<<nodeWarpBlocks, 256>>>(out, N);
}

// round 7
// speedup vs baseline: 2.5654x; 1.0948x over previous
#include <cuda_runtime.h>
#include <cuda_fp16.h>
#include <math.h>

#define NMAX 50000
#define EMAX 800000
#define ALPHA 0.01f

// ---- static scratch (no allocations allowed) ----
__device__ __half2 g_H1h[(size_t)NMAX * 128]; // layer-1 features fp16, head-major (256 halves/row)
__device__ __half2 g_H2h[(size_t)NMAX * 32];  // layer-2 features fp16 (64 halves/row)
__device__ float g_hcat[(size_t)NMAX * 256];  // elu(attention output), layer-2 input (fp32)
__device__ float g_s1h[NMAX * 4];
__device__ float g_s2h[NMAX * 4];
__device__ float g_s1o[NMAX];
__device__ float g_s2o[NMAX];
__device__ int   g_count[NMAX];               // .bss zero-init; scan_p1 re-zeroes each call
__device__ int   g_rowptr[NMAX + 1];
__device__ int   g_cursor[NMAX];
__device__ int   g_col[EMAX];
__device__ int   g_bsum[64];

// ---------------------------------------------------------------
__device__ __forceinline__ int block_probe_is64(const int* __restrict__ w, int E)
{
    int t = threadIdx.x;
    int nElem = (E < 128) ? E : 128;
    int ok = 1;
    if (t < nElem) ok = (w[2 * t + 1] == 0);
    return __syncthreads_and(ok);
}

__device__ __forceinline__ int load_idx(const int* __restrict__ w, int pos, int is64)
{
    return is64 ? w[2 * pos] : w[pos];
}

// ---------------------------------------------------------------
// tf32 tensor-core GEMM, 256-row blocks, 32 rows x 64 cols per warp.
// Fused epilogue: fp16 mirror + attention score dots.
// ---------------------------------------------------------------
__device__ __forceinline__ unsigned f2tf32(float f)
{
    unsigned u;
    asm("cvt.rna.tf32.f32 %0, %1;" : "=r"(u) : "f"(f));
    return u;
}

__device__ __forceinline__ void mma_tf32(
    float* d,
    unsigned a0, unsigned a1, unsigned a2, unsigned a3,
    unsigned b0, unsigned b1)
{
    asm volatile(
        "mma.sync.aligned.m16n8k8.row.col.f32.tf32.tf32.f32 "
        "{%0,%1,%2,%3}, {%4,%5,%6,%7}, {%8,%9}, {%0,%1,%2,%3};\n"
        : "+f"(d[0]), "+f"(d[1]), "+f"(d[2]), "+f"(d[3])
        : "r"(a0), "r"(a1), "r"(a2), "r"(a3), "r"(b0), "r"(b1));
}

#define GEMM_SMEM (128*72*4 + 2*256*20*4)   // Bs + double-buffered As = 77824 B

__global__ __launch_bounds__(256, 2) void tf32_gemm(
    const float* __restrict__ A, int lda,
    const float* __restrict__ B0, int bStride,
    const float* __restrict__ attn, int layer, int M, int K)
{
    extern __shared__ unsigned dsm[];
    unsigned (*Bs)[72] = (unsigned(*)[72])dsm;              // [128][72]
    unsigned (*As)[20] = (unsigned(*)[20])(dsm + 128 * 72); // [2*256][20]

    const float* Ap = A ? A : g_hcat;
    int head = blockIdx.y;
    const float* B = B0 + (size_t)head * bStride;
    int row0 = blockIdx.x * 256;

    int tid = threadIdx.x;
    int lane = tid & 31, w = tid >> 5;
    int gid = lane >> 2, qid = lane & 3;

    float acc0[8][4], acc1[8][4];
#pragma unroll
    for (int i = 0; i < 8; i++)
#pragma unroll
        for (int j = 0; j < 4; j++) { acc0[i][j] = 0.f; acc1[i][j] = 0.f; }

    auto stageA = [&](int koff, int buf) {
#pragma unroll
        for (int i = 0; i < 4; i++) {
            int u = tid + i * 256;
            int ar = u >> 2, c4 = (u & 3) * 4;
            float4 av = make_float4(0.f, 0.f, 0.f, 0.f);
            if (row0 + ar < M)
                av = *(const float4*)(Ap + (size_t)(row0 + ar) * lda + koff + c4);
            unsigned* dstp = &As[(buf << 8) + ar][c4];
            dstp[0] = f2tf32(av.x);
            dstp[1] = f2tf32(av.y);
            dstp[2] = f2tf32(av.z);
            dstp[3] = f2tf32(av.w);
        }
    };

    for (int kc = 0; kc < K; kc += 128) {
        if (kc) __syncthreads();
        for (int i = tid; i < 128 * 16; i += 256) {
            int br = i >> 4, bc4 = (i & 15) * 4;
            float4 bv = *(const float4*)(B + (size_t)(kc + br) * 64 + bc4);
            Bs[br][bc4 + 0] = f2tf32(bv.x);
            Bs[br][bc4 + 1] = f2tf32(bv.y);
            Bs[br][bc4 + 2] = f2tf32(bv.z);
            Bs[br][bc4 + 3] = f2tf32(bv.w);
        }
        stageA(kc, 0);
        __syncthreads();

        for (int ks = 0; ks < 128; ks += 16) {
            int buf = (ks >> 4) & 1;
            if (ks + 16 < 128) stageA(kc + ks + 16, buf ^ 1);

#pragma unroll
            for (int k8 = 0; k8 < 16; k8 += 8) {
                int rb = (buf << 8) + w * 32 + gid;
                unsigned a00 = As[rb][k8 + qid];
                unsigned a01 = As[rb + 8][k8 + qid];
                unsigned a02 = As[rb][k8 + qid + 4];
                unsigned a03 = As[rb + 8][k8 + qid + 4];
                unsigned a10 = As[rb + 16][k8 + qid];
                unsigned a11 = As[rb + 24][k8 + qid];
                unsigned a12 = As[rb + 16][k8 + qid + 4];
                unsigned a13 = As[rb + 24][k8 + qid + 4];
                int krow = ks + k8 + qid;
#pragma unroll
                for (int n0 = 0; n0 < 8; n0++) {
                    unsigned b0 = Bs[krow][n0 * 8 + gid];
                    unsigned b1 = Bs[krow + 4][n0 * 8 + gid];
                    mma_tf32(acc0[n0], a00, a01, a02, a03, b0, b1);
                    mma_tf32(acc1[n0], a10, a11, a12, a13, b0, b1);
                }
            }
            __syncthreads();
        }
    }

    // ---- fused epilogue ----
    __half2* Hh2;
    int ldH2, colBase2, sStride, sOff;
    float *s1g, *s2g;
    const float* a1;
    if (layer == 0) {
        Hh2 = g_H1h; ldH2 = 128; colBase2 = head * 32;
        sStride = 4; sOff = head; s1g = g_s1h; s2g = g_s2h;
        a1 = attn + head * 128;
    } else {
        Hh2 = g_H2h; ldH2 = 32; colBase2 = 0;
        sStride = 1; sOff = 0; s1g = g_s1o; s2g = g_s2o;
        a1 = attn;
    }
    const float* a2v = a1 + 64;

    int rb = row0 + w * 32 + gid;
    int rows[4] = {rb, rb + 8, rb + 16, rb + 24};

    float d1[4] = {0.f, 0.f, 0.f, 0.f};
    float d2[4] = {0.f, 0.f, 0.f, 0.f};
#pragma unroll
    for (int n0 = 0; n0 < 8; n0++) {
        int c0 = n0 * 8 + 2 * qid;
        float w10 = __ldg(a1 + c0), w11 = __ldg(a1 + c0 + 1);
        float w20 = __ldg(a2v + c0), w21 = __ldg(a2v + c0 + 1);
        d1[0] += acc0[n0][0] * w10 + acc0[n0][1] * w11;
        d2[0] += acc0[n0][0] * w20 + acc0[n0][1] * w21;
        d1[1] += acc0[n0][2] * w10 + acc0[n0][3] * w11;
        d2[1] += acc0[n0][2] * w20 + acc0[n0][3] * w21;
        d1[2] += acc1[n0][0] * w10 + acc1[n0][1] * w11;
        d2[2] += acc1[n0][0] * w20 + acc1[n0][1] * w21;
        d1[3] += acc1[n0][2] * w10 + acc1[n0][3] * w11;
        d2[3] += acc1[n0][2] * w20 + acc1[n0][3] * w21;
    }
#pragma unroll
    for (int f = 0; f < 4; f++) {
#pragma unroll
        for (int off = 1; off < 4; off <<= 1) {
            d1[f] += __shfl_xor_sync(0xffffffffu, d1[f], off);
            d2[f] += __shfl_xor_sync(0xffffffffu, d2[f], off);
        }
    }
    if (qid == 0) {
#pragma unroll
        for (int f = 0; f < 4; f++) {
            if (rows[f] < M) {
                s1g[rows[f] * sStride + sOff] = d1[f];
                s2g[rows[f] * sStride + sOff] = d2[f];
            }
        }
    }

#pragma unroll
    for (int n0 = 0; n0 < 8; n0++) {
        int cc = colBase2 + n0 * 4 + qid;
        if (rows[0] < M)
            Hh2[(size_t)rows[0] * ldH2 + cc] = __floats2half2_rn(acc0[n0][0], acc0[n0][1]);
        if (rows[1] < M)
            Hh2[(size_t)rows[1] * ldH2 + cc] = __floats2half2_rn(acc0[n0][2], acc0[n0][3]);
        if (rows[2] < M)
            Hh2[(size_t)rows[2] * ldH2 + cc] = __floats2half2_rn(acc1[n0][0], acc1[n0][1]);
        if (rows[3] < M)
            Hh2[(size_t)rows[3] * ldH2 + cc] = __floats2half2_rn(acc1[n0][2], acc1[n0][3]);
    }
}

// ---------------------------------------------------------------
// CSR build
// ---------------------------------------------------------------
__global__ __launch_bounds__(256) void hist_kernel(const int* __restrict__ w, int E)
{
    int is64 = block_probe_is64(w, E);
    int e = blockIdx.x * blockDim.x + threadIdx.x;
    if (e >= E) return;
    atomicAdd(&g_count[load_idx(w, e, is64)], 1);
}

__global__ __launch_bounds__(1024) void scan_p1(int n)
{
    __shared__ int wsum[32];
    int t = threadIdx.x;
    int i = blockIdx.x * 1024 + t;
    int v = (i < n) ? g_count[i] : 0;
    if (i < n) g_count[i] = 0;            // self-clear for next call
    int lane = t & 31, w = t >> 5;

    int x = v;
#pragma unroll
    for (int off = 1; off < 32; off <<= 1) {
        int y = __shfl_up_sync(0xffffffffu, x, off);
        if (lane >= off) x += y;
    }
    if (lane == 31) wsum[w] = x;
    __syncthreads();
    if (w == 0) {
        int z = wsum[lane];
#pragma unroll
        for (int off = 1; off < 32; off <<= 1) {
            int y = __shfl_up_sync(0xffffffffu, z, off);
            if (lane >= off) z += y;
        }
        wsum[lane] = z;
    }
    __syncthreads();
    int excl = x - v + (w > 0 ? wsum[w - 1] : 0);
    if (i < n) g_rowptr[i] = excl;
    if (t == 1023) g_bsum[blockIdx.x] = excl + v;
}

__global__ __launch_bounds__(1024) void scan_p3(int nb, int n)
{
    __shared__ int boff[64];
    int t = threadIdx.x;
    if (t < 64) {
        int v = (t < nb) ? g_bsum[t] : 0;
        int lane = t & 31;
        int x = v;
#pragma unroll
        for (int off = 1; off < 32; off <<= 1) {
            int y = __shfl_up_sync(0xffffffffu, x, off);
            if (lane >= off) x += y;
        }
        boff[t] = x - v;
    }
    __syncthreads();
    if (t >= 32 && t < 64)
        boff[t] += boff[31] + g_bsum[31];
    __syncthreads();

    int i = blockIdx.x * 1024 + t;
    if (i < n) {
        int val = g_rowptr[i] + boff[blockIdx.x];
        g_rowptr[i] = val;
        g_cursor[i] = val;
    }
    if (blockIdx.x == 0 && t == 0)
        g_rowptr[n] = boff[nb - 1] + g_bsum[nb - 1];
}

__global__ __launch_bounds__(256) void scatter_kernel(const int* __restrict__ w, int E)
{
    int is64 = block_probe_is64(w, E);
    int e = blockIdx.x * blockDim.x + threadIdx.x;
    if (e >= E) return;
    int src = load_idx(w, e, is64);
    int dst = load_idx(w, E + e, is64);
    int pos = atomicAdd(&g_cursor[src], 1);
    g_col[pos] = dst;
}

// ---------------------------------------------------------------
// layer-1 attention + aggregation + ELU (warp per node, 4 heads)
// single LDG.128/lane feature gather; lane L owns head L>>3, half2
// columns 4(L&7)..4(L&7)+3; scores on lanes hq=L&3; 2-edge unroll.
// ---------------------------------------------------------------
__device__ __forceinline__ float sel4(float4 v, int q)
{
    float r = v.x;
    r = (q == 1) ? v.y : r;
    r = (q == 2) ? v.z : r;
    r = (q == 3) ? v.w : r;
    return r;
}

__device__ __forceinline__ void acc_f4(float2* acc, float pm, float4 hv)
{
    __half2 q0 = *(__half2*)&hv.x;
    __half2 q1 = *(__half2*)&hv.y;
    __half2 q2 = *(__half2*)&hv.z;
    __half2 q3 = *(__half2*)&hv.w;
    float2 f0 = __half22float2(q0);
    float2 f1 = __half22float2(q1);
    float2 f2 = __half22float2(q2);
    float2 f3 = __half22float2(q3);
    acc[0].x += pm * f0.x; acc[0].y += pm * f0.y;
    acc[1].x += pm * f1.x; acc[1].y += pm * f1.y;
    acc[2].x += pm * f2.x; acc[2].y += pm * f2.y;
    acc[3].x += pm * f3.x; acc[3].y += pm * f3.y;
}

__global__ __launch_bounds__(256) void agg_heads(int N)
{
    int warp = (blockIdx.x * blockDim.x + threadIdx.x) >> 5;
    int lane = threadIdx.x & 31;
    if (warp >= N) return;

    int e0 = g_rowptr[warp];
    int e1 = g_rowptr[warp + 1];
    int hq = lane & 3;                 // head this lane scores
    int myhead = lane >> 3;            // head this lane accumulates
    float4 s1v = *(const float4*)&g_s1h[warp * 4];
    float s1q = sel4(s1v, hq);

    float lloc = 0.f;                  // sum of p for head hq
    float2 acc[4];
#pragma unroll
    for (int j = 0; j < 4; j++) acc[j] = make_float2(0.f, 0.f);

    int e = e0;
    for (; e + 2 <= e1; e += 2) {
        int da = g_col[e];
        int db = g_col[e + 1];
        float4 s2a = *(const float4*)&g_s2h[da * 4];
        float4 s2b = *(const float4*)&g_s2h[db * 4];
        float4 ha = ((const float4*)(g_H1h + (size_t)da * 128))[lane];
        float4 hb = ((const float4*)(g_H1h + (size_t)db * 128))[lane];

        float sva = s1q + sel4(s2a, hq);
        float sca = -(sva > 0.f ? sva : ALPHA * sva);
        float pa = __expf(sca);
        float svb = s1q + sel4(s2b, hq);
        float scb = -(svb > 0.f ? svb : ALPHA * svb);
        float pb = __expf(scb);
        lloc += pa;
        lloc += pb;
        float pma = __shfl_sync(0xffffffffu, pa, myhead, 4);
        float pmb = __shfl_sync(0xffffffffu, pb, myhead, 4);

        acc_f4(acc, pma, ha);
        acc_f4(acc, pmb, hb);
    }
    if (e < e1) {
        int da = g_col[e];
        float4 s2a = *(const float4*)&g_s2h[da * 4];
        float4 ha = ((const float4*)(g_H1h + (size_t)da * 128))[lane];
        float sva = s1q + sel4(s2a, hq);
        float sca = -(sva > 0.f ? sva : ALPHA * sva);
        float pa = __expf(sca);
        lloc += pa;
        float pma = __shfl_sync(0xffffffffu, pa, myhead, 4);
        acc_f4(acc, pma, ha);
    }

    float lh = __shfl_sync(0xffffffffu, lloc, myhead, 4);
    float inv = (e1 > e0) ? 1.f / lh : 0.f;

    float o[8];
#pragma unroll
    for (int j = 0; j < 4; j++) {
        o[2 * j]     = acc[j].x * inv;
        o[2 * j + 1] = acc[j].y * inv;
    }
#pragma unroll
    for (int j = 0; j < 8; j++)
        o[j] = (o[j] > 0.f) ? o[j] : (__expf(o[j]) - 1.f);   // ELU

    float* op = g_hcat + (size_t)warp * 256 + 64 * myhead + 8 * (lane & 7);
    *(float4*)op       = make_float4(o[0], o[1], o[2], o[3]);
    *(float4*)(op + 4) = make_float4(o[4], o[5], o[6], o[7]);
}

// ---------------------------------------------------------------
// output-layer aggregation (warp per node, dim 64), 2-edge unroll
// ---------------------------------------------------------------
__global__ __launch_bounds__(256) void agg_out(float* __restrict__ out, int N)
{
    int warp = (blockIdx.x * blockDim.x + threadIdx.x) >> 5;
    int lane = threadIdx.x & 31;
    if (warp >= N) return;

    int e0 = g_rowptr[warp];
    int e1 = g_rowptr[warp + 1];
    float s1 = g_s1o[warp];

    float l = 0.f;
    float2 acc = make_float2(0.f, 0.f);

    int e = e0;
    for (; e + 2 <= e1; e += 2) {
        int da = g_col[e];
        int db = g_col[e + 1];
        float s2a = g_s2o[da];
        float s2b = g_s2o[db];
        float2 va = __half22float2(g_H2h[(size_t)da * 32 + lane]);
        float2 vb = __half22float2(g_H2h[(size_t)db * 32 + lane]);

        float sva = s1 + s2a;
        float sca = -(sva > 0.f ? sva : ALPHA * sva);
        float pa = __expf(sca);
        float svb = s1 + s2b;
        float scb = -(svb > 0.f ? svb : ALPHA * svb);
        float pb = __expf(scb);
        l += pa;
        l += pb;
        acc.x += pa * va.x + pb * vb.x;
        acc.y += pa * va.y + pb * vb.y;
    }
    if (e < e1) {
        int da = g_col[e];
        float s2a = g_s2o[da];
        float2 va = __half22float2(g_H2h[(size_t)da * 32 + lane]);
        float sva = s1 + s2a;
        float sca = -(sva > 0.f ? sva : ALPHA * sva);
        float pa = __expf(sca);
        l += pa;
        acc.x += pa * va.x;
        acc.y += pa * va.y;
    }

    float va = 0.f, vb = 0.f;
    if (e1 > e0) {
        float inv = 1.f / l;
        va = acc.x * inv;
        vb = acc.y * inv;
    }
    *(float2*)(out + (size_t)warp * 64 + 2 * lane) = make_float2(va, vb);
}

// ---------------------------------------------------------------
extern "C" void kernel_launch(void* const* d_in, const int* in_sizes, int n_in,
                              void* d_out, int out_size)
{
    const float* x          = (const float*)d_in[0];
    const int*   ei_w       = (const int*)d_in[1];
    const float* W_heads    = (const float*)d_in[2];
    const float* attn_heads = (const float*)d_in[3];
    const float* W_out      = (const float*)d_in[4];
    const float* attn_out   = (const float*)d_in[5];
    float* out = (float*)d_out;

    int N = in_sizes[0] / 128;
    int E = in_sizes[1] / 2;

    int nodeWarpBlocks = (N + 7) / 8;
    int edgeBlocks = (E + 255) / 256;
    int scanBlocks = (N + 1023) / 1024;

    // one-time setup (first call is NOT under capture)
    static cudaStream_t sSide = nullptr;
    static cudaEvent_t evFork = nullptr, evJoin = nullptr;
    if (!sSide) {
        cudaStreamCreateWithFlags(&sSide, cudaStreamNonBlocking);
        cudaEventCreateWithFlags(&evFork, cudaEventDisableTiming);
        cudaEventCreateWithFlags(&evJoin, cudaEventDisableTiming);
        cudaFuncSetAttribute(tf32_gemm, cudaFuncAttributeMaxDynamicSharedMemorySize, GEMM_SMEM);
    }

    // fork: CSR chain on side stream, GEMM1 on main stream
    cudaEventRecord(evFork, 0);
    cudaStreamWaitEvent(sSide, evFork, 0);

    hist_kernel<<<edgeBlocks, 256, 0, sSide>>>(ei_w, E);    // launch 1
    scan_p1<<<scanBlocks, 1024, 0, sSide>>>(N);             // launch 2
    scan_p3<<<scanBlocks, 1024, 0, sSide>>>(scanBlocks, N); // launch 3

    // GEMM1 (+ fused svec + fp16 mirror) — launch 4 (ncu slot)
    dim3 g1((N + 255) / 256, 4);
    tf32_gemm<<<g1, 256, GEMM_SMEM>>>(x, 128, W_heads, 128 * 64, attn_heads, 0, N, 128);

    scatter_kernel<<<edgeBlocks, 256, 0, sSide>>>(ei_w, E); // launch 5
    cudaEventRecord(evJoin, sSide);

    cudaStreamWaitEvent(0, evJoin, 0);

    // layer-1 softmax+aggregate+ELU -> g_hcat
    agg_heads<<<nodeWarpBlocks, 256>>>(N);

    // GEMM2 (+ fused svec_out + fp16 mirror)
    dim3 g2((N + 255) / 256, 1);
    tf32_gemm<<<g2, 256, GEMM_SMEM>>>(nullptr, 256, W_out, 0, attn_out, 1, N, 256);

    // final aggregation
    agg_out<<<nodeWarpBlocks, 256>>>(out, N);
}

// round 9
// speedup vs baseline: 2.9077x; 1.1334x over previous
#include <cuda_runtime.h>
#include <cuda_fp16.h>
#include <math.h>

#define NMAX 50000
#define EMAX 800000
#define ALPHA 0.01f

// ---- static scratch (no allocations allowed) ----
__device__ __half2 g_H1h[(size_t)NMAX * 128]; // layer-1 features fp16, head-major (256 halves/row)
__device__ __half2 g_H2h[(size_t)NMAX * 32];  // layer-2 features fp16 (64 halves/row)
__device__ __half2 g_hcat16[(size_t)NMAX * 128]; // elu(attn out) fp16, layer-2 input
__device__ __half2 g_W16a[4 * 64 * 64];       // W_heads fp16, [head][n=64][k=128] (half2 idx)
__device__ __half2 g_W16b[64 * 128];          // W_out fp16, [n=64][k=256]
__device__ float g_s1h[NMAX * 4];
__device__ float g_s2h[NMAX * 4];
__device__ float g_s1o[NMAX];
__device__ float g_s2o[NMAX];
__device__ int   g_count[NMAX];               // .bss zero-init; scan_p1 re-zeroes each call
__device__ int   g_rowptr[NMAX + 1];
__device__ int   g_cursor[NMAX];
__device__ int   g_col[EMAX];
__device__ int   g_bsum[64];

// ---------------------------------------------------------------
__device__ __forceinline__ int block_probe_is64(const int* __restrict__ w, int E)
{
    int t = threadIdx.x;
    int nElem = (E < 128) ? E : 128;
    int ok = 1;
    if (t < nElem) ok = (w[2 * t + 1] == 0);
    return __syncthreads_and(ok);
}

__device__ __forceinline__ int load_idx(const int* __restrict__ w, int pos, int is64)
{
    return is64 ? w[2 * pos] : w[pos];
}

// ---------------------------------------------------------------
// weight prep: fp32 [k][n] -> fp16 [n][k] (transposed), once per call
// ---------------------------------------------------------------
__global__ __launch_bounds__(256) void prep_weights(
    const float* __restrict__ Wh, const float* __restrict__ Wo)
{
    int idx = blockIdx.x * 256 + threadIdx.x;
    const int T1 = 4 * 64 * 128;          // W_heads halves
    const int T2 = 64 * 256;              // W_out halves
    if (idx < T1) {
        int h = idx >> 13;                 // /8192
        int rem = idx & 8191;
        int n = rem >> 7;                  // /128
        int k = rem & 127;
        ((__half*)g_W16a)[idx] = __float2half_rn(Wh[h * 8192 + k * 64 + n]);
    } else if (idx < T1 + T2) {
        int j = idx - T1;
        int n = j >> 8;                    // /256
        int k = j & 255;
        ((__half*)g_W16b)[j] = __float2half_rn(Wo[k * 64 + n]);
    }
}

// ---------------------------------------------------------------
// fp16 tensor-core GEMM (m16n8k16, fp32 accum), 256x64 block,
// warp tile 32x64. Fused epilogue: fp16 mirror + score dots.
// All __device__ globals resolved IN KERNEL via layer flag.
// layer 0: A = A32 (x, fp32), B = g_W16a[head]
// layer 1: A = g_hcat16 (fp16), B = g_W16b
// ---------------------------------------------------------------
__device__ __forceinline__ void mma16816(
    float* d, unsigned a0, unsigned a1, unsigned a2, unsigned a3,
    unsigned b0, unsigned b1)
{
    asm volatile(
        "mma.sync.aligned.m16n8k16.row.col.f32.f16.f16.f32 "
        "{%0,%1,%2,%3}, {%4,%5,%6,%7}, {%8,%9}, {%0,%1,%2,%3};\n"
        : "+f"(d[0]), "+f"(d[1]), "+f"(d[2]), "+f"(d[3])
        : "r"(a0), "r"(a1), "r"(a2), "r"(a3), "r"(b0), "r"(b1));
}

#define ROWW 68                                  // smem words per row (136 halves)
#define GEMM_SMEM ((64 * ROWW + 256 * ROWW) * 4) // B + A = 87040 B

__global__ __launch_bounds__(256, 2) void h16_gemm(
    const float* __restrict__ A32, int lda,
    const float* __restrict__ attn, int layer, int M, int K)
{
    extern __shared__ unsigned dsm[];
    unsigned* Bs = dsm;                    // [64][ROWW]
    unsigned* As = dsm + 64 * ROWW;        // [256][ROWW]

    int head = blockIdx.y;
    // device-symbol resolution happens here, in device code
    const unsigned* Bg = (layer == 0)
        ? (const unsigned*)g_W16a + (size_t)head * 4096   // 64n x 64w per head
        : (const unsigned*)g_W16b;
    int ldbW = (layer == 0) ? 64 : 128;    // words per n-row
    const unsigned* A16 = (const unsigned*)g_hcat16;      // used when A32==null
    const int ldaW = 128;                  // g_hcat16 words per row

    int row0 = blockIdx.x * 256;

    int tid = threadIdx.x;
    int lane = tid & 31, w = tid >> 5;
    int gid = lane >> 2, tig = lane & 3;

    float acc0[8][4], acc1[8][4];
#pragma unroll
    for (int i = 0; i < 8; i++)
#pragma unroll
        for (int j = 0; j < 4; j++) { acc0[i][j] = 0.f; acc1[i][j] = 0.f; }

    for (int kc = 0; kc < K; kc += 128) {
        if (kc) __syncthreads();
        // stage B chunk: 64 n-rows x 64 words
#pragma unroll
        for (int i = 0; i < 8; i++) {
            int u = tid + i * 256;
            int n = u >> 5, w2 = u & 31;
            uint2 v = *(const uint2*)(Bg + n * ldbW + (kc >> 1) + 2 * w2);
            *(uint2*)&Bs[n * ROWW + 2 * w2] = v;
        }
        // stage A chunk: 256 rows x 64 words
        if (A32) {
#pragma unroll
            for (int i = 0; i < 32; i++) {
                int u = tid + i * 256;
                int row = u >> 5, c4 = u & 31;
                float4 av = make_float4(0.f, 0.f, 0.f, 0.f);
                if (row0 + row < M)
                    av = *(const float4*)(A32 + (size_t)(row0 + row) * lda + kc + c4 * 4);
                __half2 lo = __floats2half2_rn(av.x, av.y);
                __half2 hi = __floats2half2_rn(av.z, av.w);
                *(uint2*)&As[row * ROWW + 2 * c4] =
                    make_uint2(*(unsigned*)&lo, *(unsigned*)&hi);
            }
        } else {
#pragma unroll
            for (int i = 0; i < 32; i++) {
                int u = tid + i * 256;
                int row = u >> 5, w2 = u & 31;
                uint2 v = make_uint2(0u, 0u);
                if (row0 + row < M)
                    v = *(const uint2*)(A16 + (size_t)(row0 + row) * ldaW + (kc >> 1) + 2 * w2);
                *(uint2*)&As[row * ROWW + 2 * w2] = v;
            }
        }
        __syncthreads();

#pragma unroll
        for (int s = 0; s < 8; s++) {          // 8 k16 steps per 128-half chunk
            int ws = s * 8;
            int rA = (w * 32 + gid) * ROWW;
            unsigned a00 = As[rA + ws + tig];
            unsigned a01 = As[rA + 8 * ROWW + ws + tig];
            unsigned a02 = As[rA + ws + 4 + tig];
            unsigned a03 = As[rA + 8 * ROWW + ws + 4 + tig];
            unsigned a10 = As[rA + 16 * ROWW + ws + tig];
            unsigned a11 = As[rA + 24 * ROWW + ws + tig];
            unsigned a12 = As[rA + 16 * ROWW + ws + 4 + tig];
            unsigned a13 = As[rA + 24 * ROWW + ws + 4 + tig];
#pragma unroll
            for (int n0 = 0; n0 < 8; n0++) {
                int rB = (n0 * 8 + gid) * ROWW + ws + tig;
                unsigned b0 = Bs[rB];
                unsigned b1 = Bs[rB + 4];
                mma16816(acc0[n0], a00, a01, a02, a03, b0, b1);
                mma16816(acc1[n0], a10, a11, a12, a13, b0, b1);
            }
        }
    }

    // ---- fused epilogue ----
    __half2* Hh2;
    int ldH2, colBase2, sStride, sOff;
    float *s1g, *s2g;
    const float* a1;
    if (layer == 0) {
        Hh2 = g_H1h; ldH2 = 128; colBase2 = head * 32;
        sStride = 4; sOff = head; s1g = g_s1h; s2g = g_s2h;
        a1 = attn + head * 128;
    } else {
        Hh2 = g_H2h; ldH2 = 32; colBase2 = 0;
        sStride = 1; sOff = 0; s1g = g_s1o; s2g = g_s2o;
        a1 = attn;
    }
    const float* a2v = a1 + 64;

    int rb = row0 + w * 32 + gid;
    int rows[4] = {rb, rb + 8, rb + 16, rb + 24};

    float d1[4] = {0.f, 0.f, 0.f, 0.f};
    float d2[4] = {0.f, 0.f, 0.f, 0.f};
#pragma unroll
    for (int n0 = 0; n0 < 8; n0++) {
        int c0 = n0 * 8 + 2 * tig;
        float w10 = __ldg(a1 + c0), w11 = __ldg(a1 + c0 + 1);
        float w20 = __ldg(a2v + c0), w21 = __ldg(a2v + c0 + 1);
        d1[0] += acc0[n0][0] * w10 + acc0[n0][1] * w11;
        d2[0] += acc0[n0][0] * w20 + acc0[n0][1] * w21;
        d1[1] += acc0[n0][2] * w10 + acc0[n0][3] * w11;
        d2[1] += acc0[n0][2] * w20 + acc0[n0][3] * w21;
        d1[2] += acc1[n0][0] * w10 + acc1[n0][1] * w11;
        d2[2] += acc1[n0][0] * w20 + acc1[n0][1] * w21;
        d1[3] += acc1[n0][2] * w10 + acc1[n0][3] * w11;
        d2[3] += acc1[n0][2] * w20 + acc1[n0][3] * w21;
    }
#pragma unroll
    for (int f = 0; f < 4; f++) {
#pragma unroll
        for (int off = 1; off < 4; off <<= 1) {
            d1[f] += __shfl_xor_sync(0xffffffffu, d1[f], off);
            d2[f] += __shfl_xor_sync(0xffffffffu, d2[f], off);
        }
    }
    if (tig == 0) {
#pragma unroll
        for (int f = 0; f < 4; f++) {
            if (rows[f] < M) {
                s1g[rows[f] * sStride + sOff] = d1[f];
                s2g[rows[f] * sStride + sOff] = d2[f];
            }
        }
    }

#pragma unroll
    for (int n0 = 0; n0 < 8; n0++) {
        int cc = colBase2 + n0 * 4 + tig;
        if (rows[0] < M)
            Hh2[(size_t)rows[0] * ldH2 + cc] = __floats2half2_rn(acc0[n0][0], acc0[n0][1]);
        if (rows[1] < M)
            Hh2[(size_t)rows[1] * ldH2 + cc] = __floats2half2_rn(acc0[n0][2], acc0[n0][3]);
        if (rows[2] < M)
            Hh2[(size_t)rows[2] * ldH2 + cc] = __floats2half2_rn(acc1[n0][0], acc1[n0][1]);
        if (rows[3] < M)
            Hh2[(size_t)rows[3] * ldH2 + cc] = __floats2half2_rn(acc1[n0][2], acc1[n0][3]);
    }
}

// ---------------------------------------------------------------
// CSR build
// ---------------------------------------------------------------
__global__ __launch_bounds__(256) void hist_kernel(const int* __restrict__ w, int E)
{
    int is64 = block_probe_is64(w, E);
    int e = blockIdx.x * blockDim.x + threadIdx.x;
    if (e >= E) return;
    atomicAdd(&g_count[load_idx(w, e, is64)], 1);
}

__global__ __launch_bounds__(1024) void scan_p1(int n)
{
    __shared__ int wsum[32];
    int t = threadIdx.x;
    int i = blockIdx.x * 1024 + t;
    int v = (i < n) ? g_count[i] : 0;
    if (i < n) g_count[i] = 0;            // self-clear for next call
    int lane = t & 31, w = t >> 5;

    int x = v;
#pragma unroll
    for (int off = 1; off < 32; off <<= 1) {
        int y = __shfl_up_sync(0xffffffffu, x, off);
        if (lane >= off) x += y;
    }
    if (lane == 31) wsum[w] = x;
    __syncthreads();
    if (w == 0) {
        int z = wsum[lane];
#pragma unroll
        for (int off = 1; off < 32; off <<= 1) {
            int y = __shfl_up_sync(0xffffffffu, z, off);
            if (lane >= off) z += y;
        }
        wsum[lane] = z;
    }
    __syncthreads();
    int excl = x - v + (w > 0 ? wsum[w - 1] : 0);
    if (i < n) g_rowptr[i] = excl;
    if (t == 1023) g_bsum[blockIdx.x] = excl + v;
}

__global__ __launch_bounds__(1024) void scan_p3(int nb, int n)
{
    __shared__ int boff[64];
    int t = threadIdx.x;
    if (t < 64) {
        int v = (t < nb) ? g_bsum[t] : 0;
        int lane = t & 31;
        int x = v;
#pragma unroll
        for (int off = 1; off < 32; off <<= 1) {
            int y = __shfl_up_sync(0xffffffffu, x, off);
            if (lane >= off) x += y;
        }
        boff[t] = x - v;
    }
    __syncthreads();
    if (t >= 32 && t < 64)
        boff[t] += boff[31] + g_bsum[31];
    __syncthreads();

    int i = blockIdx.x * 1024 + t;
    if (i < n) {
        int val = g_rowptr[i] + boff[blockIdx.x];
        g_rowptr[i] = val;
        g_cursor[i] = val;
    }
    if (blockIdx.x == 0 && t == 0)
        g_rowptr[n] = boff[nb - 1] + g_bsum[nb - 1];
}

__global__ __launch_bounds__(256) void scatter_kernel(const int* __restrict__ w, int E)
{
    int is64 = block_probe_is64(w, E);
    int e = blockIdx.x * blockDim.x + threadIdx.x;
    if (e >= E) return;
    int src = load_idx(w, e, is64);
    int dst = load_idx(w, E + e, is64);
    int pos = atomicAdd(&g_cursor[src], 1);
    g_col[pos] = dst;
}

// ---------------------------------------------------------------
// layer-1 attention + aggregation + ELU (warp per node, 4 heads)
// single LDG.128/lane feature gather; 2-edge unroll; fp16 hcat out.
// ---------------------------------------------------------------
__device__ __forceinline__ float sel4(float4 v, int q)
{
    float r = v.x;
    r = (q == 1) ? v.y : r;
    r = (q == 2) ? v.z : r;
    r = (q == 3) ? v.w : r;
    return r;
}

__device__ __forceinline__ void acc_f4(float2* acc, float pm, float4 hv)
{
    __half2 q0 = *(__half2*)&hv.x;
    __half2 q1 = *(__half2*)&hv.y;
    __half2 q2 = *(__half2*)&hv.z;
    __half2 q3 = *(__half2*)&hv.w;
    float2 f0 = __half22float2(q0);
    float2 f1 = __half22float2(q1);
    float2 f2 = __half22float2(q2);
    float2 f3 = __half22float2(q3);
    acc[0].x += pm * f0.x; acc[0].y += pm * f0.y;
    acc[1].x += pm * f1.x; acc[1].y += pm * f1.y;
    acc[2].x += pm * f2.x; acc[2].y += pm * f2.y;
    acc[3].x += pm * f3.x; acc[3].y += pm * f3.y;
}

__global__ __launch_bounds__(256) void agg_heads(int N)
{
    int warp = (blockIdx.x * blockDim.x + threadIdx.x) >> 5;
    int lane = threadIdx.x & 31;
    if (warp >= N) return;

    int e0 = g_rowptr[warp];
    int e1 = g_rowptr[warp + 1];
    int hq = lane & 3;                 // head this lane scores
    int myhead = lane >> 3;            // head this lane accumulates
    float4 s1v = *(const float4*)&g_s1h[warp * 4];
    float s1q = sel4(s1v, hq);

    float lloc = 0.f;
    float2 acc[4];
#pragma unroll
    for (int j = 0; j < 4; j++) acc[j] = make_float2(0.f, 0.f);

    int e = e0;
    for (; e + 2 <= e1; e += 2) {
        int da = g_col[e];
        int db = g_col[e + 1];
        float4 s2a = *(const float4*)&g_s2h[da * 4];
        float4 s2b = *(const float4*)&g_s2h[db * 4];
        float4 ha = ((const float4*)(g_H1h + (size_t)da * 128))[lane];
        float4 hb = ((const float4*)(g_H1h + (size_t)db * 128))[lane];

        float sva = s1q + sel4(s2a, hq);
        float sca = -(sva > 0.f ? sva : ALPHA * sva);
        float pa = __expf(sca);
        float svb = s1q + sel4(s2b, hq);
        float scb = -(svb > 0.f ? svb : ALPHA * svb);
        float pb = __expf(scb);
        lloc += pa;
        lloc += pb;
        float pma = __shfl_sync(0xffffffffu, pa, myhead, 4);
        float pmb = __shfl_sync(0xffffffffu, pb, myhead, 4);

        acc_f4(acc, pma, ha);
        acc_f4(acc, pmb, hb);
    }
    if (e < e1) {
        int da = g_col[e];
        float4 s2a = *(const float4*)&g_s2h[da * 4];
        float4 ha = ((const float4*)(g_H1h + (size_t)da * 128))[lane];
        float sva = s1q + sel4(s2a, hq);
        float sca = -(sva > 0.f ? sva : ALPHA * sva);
        float pa = __expf(sca);
        lloc += pa;
        float pma = __shfl_sync(0xffffffffu, pa, myhead, 4);
        acc_f4(acc, pma, ha);
    }

    float lh = __shfl_sync(0xffffffffu, lloc, myhead, 4);
    float inv = (e1 > e0) ? 1.f / lh : 0.f;

    float o[8];
#pragma unroll
    for (int j = 0; j < 4; j++) {
        o[2 * j]     = acc[j].x * inv;
        o[2 * j + 1] = acc[j].y * inv;
    }
#pragma unroll
    for (int j = 0; j < 8; j++)
        o[j] = (o[j] > 0.f) ? o[j] : (__expf(o[j]) - 1.f);   // ELU

    __half2 oh[4];
#pragma unroll
    for (int j = 0; j < 4; j++)
        oh[j] = __floats2half2_rn(o[2 * j], o[2 * j + 1]);
    __half2* op = g_hcat16 + (size_t)warp * 128 + myhead * 32 + 4 * (lane & 7);
    op[0] = oh[0]; op[1] = oh[1]; op[2] = oh[2]; op[3] = oh[3];
}

// ---------------------------------------------------------------
// output-layer aggregation (warp per node, dim 64), 2-edge unroll
// ---------------------------------------------------------------
__global__ __launch_bounds__(256) void agg_out(float* __restrict__ out, int N)
{
    int warp = (blockIdx.x * blockDim.x + threadIdx.x) >> 5;
    int lane = threadIdx.x & 31;
    if (warp >= N) return;

    int e0 = g_rowptr[warp];
    int e1 = g_rowptr[warp + 1];
    float s1 = g_s1o[warp];

    float l = 0.f;
    float2 acc = make_float2(0.f, 0.f);

    int e = e0;
    for (; e + 2 <= e1; e += 2) {
        int da = g_col[e];
        int db = g_col[e + 1];
        float s2a = g_s2o[da];
        float s2b = g_s2o[db];
        float2 va = __half22float2(g_H2h[(size_t)da * 32 + lane]);
        float2 vb = __half22float2(g_H2h[(size_t)db * 32 + lane]);

        float sva = s1 + s2a;
        float sca = -(sva > 0.f ? sva : ALPHA * sva);
        float pa = __expf(sca);
        float svb = s1 + s2b;
        float scb = -(svb > 0.f ? svb : ALPHA * svb);
        float pb = __expf(scb);
        l += pa;
        l += pb;
        acc.x += pa * va.x + pb * vb.x;
        acc.y += pa * va.y + pb * vb.y;
    }
    if (e < e1) {
        int da = g_col[e];
        float s2a = g_s2o[da];
        float2 va = __half22float2(g_H2h[(size_t)da * 32 + lane]);
        float sva = s1 + s2a;
        float sca = -(sva > 0.f ? sva : ALPHA * sva);
        float pa = __expf(sca);
        l += pa;
        acc.x += pa * va.x;
        acc.y += pa * va.y;
    }

    float va = 0.f, vb = 0.f;
    if (e1 > e0) {
        float inv = 1.f / l;
        va = acc.x * inv;
        vb = acc.y * inv;
    }
    *(float2*)(out + (size_t)warp * 64 + 2 * lane) = make_float2(va, vb);
}

// ---------------------------------------------------------------
extern "C" void kernel_launch(void* const* d_in, const int* in_sizes, int n_in,
                              void* d_out, int out_size)
{
    const float* x          = (const float*)d_in[0];
    const int*   ei_w       = (const int*)d_in[1];
    const float* W_heads    = (const float*)d_in[2];
    const float* attn_heads = (const float*)d_in[3];
    const float* W_out      = (const float*)d_in[4];
    const float* attn_out   = (const float*)d_in[5];
    float* out = (float*)d_out;

    int N = in_sizes[0] / 128;
    int E = in_sizes[1] / 2;

    int nodeWarpBlocks = (N + 7) / 8;
    int edgeBlocks = (E + 255) / 256;
    int scanBlocks = (N + 1023) / 1024;

    // one-time setup (first call is NOT under capture)
    static cudaStream_t sSide = nullptr;
    static cudaEvent_t evFork = nullptr, evJoin = nullptr;
    if (!sSide) {
        cudaStreamCreateWithFlags(&sSide, cudaStreamNonBlocking);
        cudaEventCreateWithFlags(&evFork, cudaEventDisableTiming);
        cudaEventCreateWithFlags(&evJoin, cudaEventDisableTiming);
        cudaFuncSetAttribute(h16_gemm, cudaFuncAttributeMaxDynamicSharedMemorySize, GEMM_SMEM);
    }

    // fork: CSR chain on side stream, weights-prep + GEMM1 on main stream
    cudaEventRecord(evFork, 0);
    cudaStreamWaitEvent(sSide, evFork, 0);

    hist_kernel<<<edgeBlocks, 256, 0, sSide>>>(ei_w, E);
    scan_p1<<<scanBlocks, 1024, 0, sSide>>>(N);
    scan_p3<<<scanBlocks, 1024, 0, sSide>>>(scanBlocks, N);

    prep_weights<<<192, 256>>>(W_heads, W_out);

    // GEMM1 (+ fused svec + fp16 mirror): 4 head tiles
    dim3 g1((N + 255) / 256, 4);
    h16_gemm<<<g1, 256, GEMM_SMEM>>>(x, 128, attn_heads, /*layer=*/0, N, 128);

    scatter_kernel<<<edgeBlocks, 256, 0, sSide>>>(ei_w, E);
    cudaEventRecord(evJoin, sSide);

    cudaStreamWaitEvent(0, evJoin, 0);

    // layer-1 softmax+aggregate+ELU -> g_hcat16
    agg_heads<<<nodeWarpBlocks, 256>>>(N);

    // GEMM2 (+ fused svec_out + fp16 mirror)
    dim3 g2((N + 255) / 256, 1);
    h16_gemm<<<g2, 256, GEMM_SMEM>>>(nullptr, 0, attn_out, /*layer=*/1, N, 256);

    // final aggregation
    agg_out<<<nodeWarpBlocks, 256>>>(out, N);
}